// round 4
// baseline (speedup 1.0000x reference)
#include <cuda_runtime.h>
#include <cuda_fp16.h>

#define NN 100000
#define NE 1600000
#define NF 128
#define NH 64
#define NC 40

#define SCAN_B 1024
#define NBLK ((NN + SCAN_B - 1) / SCAN_B)   // 98

#define XS_STRIDE (NF + 4)
#define AS_STRIDE (NH + 4)
#define WT_STRIDE (NH + 4)

// ---------------- scratch ----------------
__device__ int     g_is64;
__device__ int     g_src[NE];
__device__ int     g_dst[NE];
__device__ float   g_degw[NN];
__device__ int     g_cnt[NN];
__device__ int     g_rowptr[NN];
__device__ int     g_fill[NN];
__device__ float   g_dinv[NN];
__device__ int2    g_edge[NE];          // CSR: {src, float_bits(norm)}
__device__ __half2 g_h1h[NN * 32];      // h1 in fp16, 32 half2 per row
__device__ float   g_a1[NN * NH];
__device__ float   g_h2[NN * NC];
__device__ int     g_bsum[NBLK];

// ---------------- f32x2 helpers ----------------
__device__ __forceinline__ unsigned long long splat2(float v) {
    unsigned long long r;
    unsigned int b = __float_as_uint(v);
    asm("mov.b64 %0, {%1, %1};" : "=l"(r) : "r"(b));
    return r;
}
__device__ __forceinline__ void fma2(unsigned long long& d,
                                     unsigned long long a,
                                     unsigned long long b) {
    asm("fma.rn.f32x2 %0, %1, %2, %0;" : "+l"(d) : "l"(a), "l"(b));
}
__device__ __forceinline__ float2 unpack2(unsigned long long v) {
    float2 f;
    asm("mov.b64 {%0, %1}, %2;" : "=f"(f.x), "=f"(f.y) : "l"(v));
    return f;
}
__device__ __forceinline__ unsigned h2bits(__half2 h) {
    return *(unsigned*)&h;
}

// ---------------- dtype detection ----------------
__global__ void k_detect(const long long* __restrict__ ei) {
    __shared__ int ok;
    if (threadIdx.x == 0) ok = 1;
    __syncthreads();
    long long v = ei[threadIdx.x];
    if (!(v >= 0 && v < (long long)NN)) atomicAnd(&ok, 0);
    __syncthreads();
    if (threadIdx.x == 0) g_is64 = ok;
}

// ---------------- fused decode + degree/count ----------------
__global__ void k_decode_deg(const void* __restrict__ ei, const float* __restrict__ w) {
    int e = blockIdx.x * blockDim.x + threadIdx.x;
    if (e >= NE) return;
    int s, d;
    if (g_is64) {
        const long long* p = (const long long*)ei;
        s = (int)p[e]; d = (int)p[NE + e];
    } else {
        const int* p = (const int*)ei;
        s = p[e]; d = p[NE + e];
    }
    g_src[e] = s;
    g_dst[e] = d;
    atomicAdd(&g_degw[d], w[e]);
    atomicAdd(&g_cnt[d], 1);
}

// ---------------- scan ----------------
__global__ void k_scan1() {
    __shared__ int s[SCAN_B];
    int gid = blockIdx.x * SCAN_B + threadIdx.x;
    int v = (gid < NN) ? g_cnt[gid] : 0;
    s[threadIdx.x] = v;
    __syncthreads();
    for (int off = 1; off < SCAN_B; off <<= 1) {
        int t = (threadIdx.x >= off) ? s[threadIdx.x - off] : 0;
        __syncthreads();
        s[threadIdx.x] += t;
        __syncthreads();
    }
    int incl = s[threadIdx.x];
    if (gid < NN) g_rowptr[gid] = incl - v;
    if (threadIdx.x == SCAN_B - 1) g_bsum[blockIdx.x] = incl;
}

__global__ void k_scan2() {
    __shared__ int s[128];
    int t = threadIdx.x;
    int v = (t < NBLK) ? g_bsum[t] : 0;
    s[t] = v;
    __syncthreads();
    #pragma unroll
    for (int off = 1; off < 128; off <<= 1) {
        int u = (t >= off) ? s[t - off] : 0;
        __syncthreads();
        s[t] += u;
        __syncthreads();
    }
    if (t < NBLK) g_bsum[t] = s[t] - v;   // exclusive
}

__global__ void k_scan3() {
    int gid = blockIdx.x * SCAN_B + threadIdx.x;
    if (gid >= NN) return;
    int rp = g_rowptr[gid] + g_bsum[blockIdx.x];
    g_rowptr[gid] = rp;
    g_fill[gid]   = rp;
    g_dinv[gid]   = rsqrtf(g_degw[gid] + 1.0f);
}

// ---------------- CSR fill ----------------
__global__ void k_fill(const float* __restrict__ w) {
    int e = blockIdx.x * blockDim.x + threadIdx.x;
    if (e >= NE) return;
    int s = g_src[e], d = g_dst[e];
    int pos = atomicAdd(&g_fill[d], 1);
    float nv = g_dinv[s] * w[e] * g_dinv[d];
    g_edge[pos] = make_int2(s, __float_as_int(nv));
}

// ---------------- GEMM1: h1 = x @ W1, f32x2 packed, fp16 output ----------------
__global__ __launch_bounds__(256) void k_gemm1(const float* __restrict__ x,
                                               const float* __restrict__ W1) {
    __shared__ float Ws[NF * NH];            // 32 KB
    __shared__ float xs[64 * XS_STRIDE];     // ~33 KB
    int tid = threadIdx.x;
    int row0 = blockIdx.x * 64;

    const float4* W4 = (const float4*)W1;
    float4* Ws4 = (float4*)Ws;
    #pragma unroll
    for (int i = tid; i < (NF * NH) / 4; i += 256) Ws4[i] = W4[i];

    const float4* x4 = (const float4*)x;
    int base4 = row0 * (NF / 4);
    int limit4 = (NN - row0) * (NF / 4);
    #pragma unroll
    for (int i = tid; i < 64 * (NF / 4); i += 256) {
        int rr = i >> 5;
        int cc = i & 31;
        float4 v = (i < limit4) ? x4[base4 + i] : make_float4(0.f, 0.f, 0.f, 0.f);
        *(float4*)&xs[rr * XS_STRIDE + cc * 4] = v;
    }
    __syncthreads();

    int r  = tid >> 3;        // 0..31
    int cg = tid & 7;         // 8 cols each (4 f32x2)
    unsigned long long acc0[4] = {0ull, 0ull, 0ull, 0ull};
    unsigned long long acc1[4] = {0ull, 0ull, 0ull, 0ull};
    const float* xr0 = &xs[r * XS_STRIDE];
    const float* xr1 = &xs[(r + 32) * XS_STRIDE];
    #pragma unroll 4
    for (int k = 0; k < NF; k++) {
        unsigned long long xp0 = splat2(xr0[k]);
        unsigned long long xp1 = splat2(xr1[k]);
        ulonglong2 wa = *(const ulonglong2*)&Ws[k * NH + cg * 8];
        ulonglong2 wb = *(const ulonglong2*)&Ws[k * NH + cg * 8 + 4];
        fma2(acc0[0], xp0, wa.x); fma2(acc0[1], xp0, wa.y);
        fma2(acc0[2], xp0, wb.x); fma2(acc0[3], xp0, wb.y);
        fma2(acc1[0], xp1, wa.x); fma2(acc1[1], xp1, wa.y);
        fma2(acc1[2], xp1, wb.x); fma2(acc1[3], xp1, wb.y);
    }
    int r0g = row0 + r, r1g = row0 + r + 32;
    if (r0g < NN) {
        uint4 st;
        st.x = h2bits(__float22half2_rn(unpack2(acc0[0])));
        st.y = h2bits(__float22half2_rn(unpack2(acc0[1])));
        st.z = h2bits(__float22half2_rn(unpack2(acc0[2])));
        st.w = h2bits(__float22half2_rn(unpack2(acc0[3])));
        *(uint4*)(g_h1h + (size_t)r0g * 32 + cg * 4) = st;
    }
    if (r1g < NN) {
        uint4 st;
        st.x = h2bits(__float22half2_rn(unpack2(acc1[0])));
        st.y = h2bits(__float22half2_rn(unpack2(acc1[1])));
        st.z = h2bits(__float22half2_rn(unpack2(acc1[2])));
        st.w = h2bits(__float22half2_rn(unpack2(acc1[3])));
        *(uint4*)(g_h1h + (size_t)r1g * 32 + cg * 4) = st;
    }
}

// ---------------- AGG1: fp16 gather + bias + relu -> a1 (fp32) ----------------
__global__ __launch_bounds__(256) void k_agg1(const float* __restrict__ b1) {
    int node = (blockIdx.x * blockDim.x + threadIdx.x) >> 5;
    int lane = threadIdx.x & 31;
    if (node >= NN) return;
    int beg = g_rowptr[node];
    int end = beg + g_cnt[node];
    float di = g_dinv[node];
    float self = di * di;
    float2 hf = __half22float2(g_h1h[(size_t)node * 32 + lane]);
    float a0 = self * hf.x;
    float a1 = self * hf.y;

    int e = beg;
    for (; e + 3 < end; e += 4) {
        int2 e0 = g_edge[e],     e1 = g_edge[e + 1];
        int2 e2 = g_edge[e + 2], e3 = g_edge[e + 3];
        __half2 v0 = g_h1h[(size_t)e0.x * 32 + lane];
        __half2 v1 = g_h1h[(size_t)e1.x * 32 + lane];
        __half2 v2 = g_h1h[(size_t)e2.x * 32 + lane];
        __half2 v3 = g_h1h[(size_t)e3.x * 32 + lane];
        float n0 = __int_as_float(e0.y), n1 = __int_as_float(e1.y);
        float n2 = __int_as_float(e2.y), n3 = __int_as_float(e3.y);
        float2 f0 = __half22float2(v0), f1 = __half22float2(v1);
        float2 f2 = __half22float2(v2), f3 = __half22float2(v3);
        a0 = fmaf(n0, f0.x, a0); a1 = fmaf(n0, f0.y, a1);
        a0 = fmaf(n1, f1.x, a0); a1 = fmaf(n1, f1.y, a1);
        a0 = fmaf(n2, f2.x, a0); a1 = fmaf(n2, f2.y, a1);
        a0 = fmaf(n3, f3.x, a0); a1 = fmaf(n3, f3.y, a1);
    }
    for (; e < end; e++) {
        int2 ed = g_edge[e];
        float n = __int_as_float(ed.y);
        float2 f = __half22float2(g_h1h[(size_t)ed.x * 32 + lane]);
        a0 = fmaf(n, f.x, a0); a1 = fmaf(n, f.y, a1);
    }
    float2 bb = *(const float2*)&b1[2 * lane];
    a0 += bb.x;
    a1 += bb.y;
    float2 st = make_float2(fmaxf(a0, 0.f), fmaxf(a1, 0.f));
    *(float2*)&g_a1[(size_t)node * NH + 2 * lane] = st;
}

// ---------------- GEMM2: h2 = a1 @ W2 ----------------
__global__ __launch_bounds__(256) void k_gemm2(const float* __restrict__ W2) {
    __shared__ float WsT[NC * WT_STRIDE];
    __shared__ float as[64 * AS_STRIDE];
    int tid = threadIdx.x;
    int row0 = blockIdx.x * 64;

    for (int i = tid; i < NH * NC; i += 256) {
        int k = i / NC, c = i % NC;
        WsT[c * WT_STRIDE + k] = W2[i];
    }
    const float4* a4 = (const float4*)g_a1 + row0 * (NH / 4);
    int limit4 = (NN - row0) * (NH / 4);
    for (int i = tid; i < 64 * (NH / 4); i += 256) {
        int rr = i >> 4;
        int cc = i & 15;
        float4 v = (i < limit4) ? a4[i] : make_float4(0.f, 0.f, 0.f, 0.f);
        *(float4*)&as[rr * AS_STRIDE + cc * 4] = v;
    }
    __syncthreads();

    int r  = tid >> 3;
    int cg = tid & 7;
    float acc0[5] = {0, 0, 0, 0, 0};
    float acc1[5] = {0, 0, 0, 0, 0};
    const float* ar0 = &as[r * AS_STRIDE];
    const float* ar1 = &as[(r + 32) * AS_STRIDE];
    #pragma unroll
    for (int kk = 0; kk < NH / 4; kk++) {
        float4 av0 = *(const float4*)&ar0[kk * 4];
        float4 av1 = *(const float4*)&ar1[kk * 4];
        #pragma unroll
        for (int j = 0; j < 5; j++) {
            float4 w = *(const float4*)&WsT[(cg * 5 + j) * WT_STRIDE + kk * 4];
            acc0[j] += av0.x * w.x + av0.y * w.y + av0.z * w.z + av0.w * w.w;
            acc1[j] += av1.x * w.x + av1.y * w.y + av1.z * w.z + av1.w * w.w;
        }
    }
    int r0g = row0 + r, r1g = row0 + r + 32;
    if (r0g < NN) {
        float* o = g_h2 + (size_t)r0g * NC + cg * 5;
        #pragma unroll
        for (int j = 0; j < 5; j++) o[j] = acc0[j];
    }
    if (r1g < NN) {
        float* o = g_h2 + (size_t)r1g * NC + cg * 5;
        #pragma unroll
        for (int j = 0; j < 5; j++) o[j] = acc1[j];
    }
}

// ---------------- AGG2 + bias + log_softmax ----------------
__global__ __launch_bounds__(256) void k_agg2(const float* __restrict__ b2,
                                              float* __restrict__ out) {
    int node = (blockIdx.x * blockDim.x + threadIdx.x) >> 5;
    int lane = threadIdx.x & 31;
    if (node >= NN) return;
    bool hi = (lane < NC - 32);
    int beg = g_rowptr[node];
    int end = beg + g_cnt[node];
    float di = g_dinv[node];
    float self = di * di;
    const float* hn = &g_h2[(size_t)node * NC];
    float a0 = self * hn[lane];
    float a1 = hi ? self * hn[32 + lane] : 0.f;

    int e = beg;
    for (; e + 3 < end; e += 4) {
        int2 e0 = g_edge[e],     e1 = g_edge[e + 1];
        int2 e2 = g_edge[e + 2], e3 = g_edge[e + 3];
        const float* p0 = &g_h2[(size_t)e0.x * NC];
        const float* p1 = &g_h2[(size_t)e1.x * NC];
        const float* p2 = &g_h2[(size_t)e2.x * NC];
        const float* p3 = &g_h2[(size_t)e3.x * NC];
        float n0 = __int_as_float(e0.y), n1 = __int_as_float(e1.y);
        float n2 = __int_as_float(e2.y), n3 = __int_as_float(e3.y);
        float v0 = p0[lane], v1 = p1[lane], v2 = p2[lane], v3 = p3[lane];
        a0 = fmaf(n0, v0, a0); a0 = fmaf(n1, v1, a0);
        a0 = fmaf(n2, v2, a0); a0 = fmaf(n3, v3, a0);
        if (hi) {
            float u0 = p0[32 + lane], u1 = p1[32 + lane];
            float u2 = p2[32 + lane], u3 = p3[32 + lane];
            a1 = fmaf(n0, u0, a1); a1 = fmaf(n1, u1, a1);
            a1 = fmaf(n2, u2, a1); a1 = fmaf(n3, u3, a1);
        }
    }
    for (; e < end; e++) {
        int2 ed = g_edge[e];
        const float* p = &g_h2[(size_t)ed.x * NC];
        float n = __int_as_float(ed.y);
        a0 = fmaf(n, p[lane], a0);
        if (hi) a1 = fmaf(n, p[32 + lane], a1);
    }
    a0 += b2[lane];
    if (hi) a1 += b2[32 + lane];

    float m = hi ? fmaxf(a0, a1) : a0;
    #pragma unroll
    for (int off = 16; off > 0; off >>= 1)
        m = fmaxf(m, __shfl_xor_sync(0xffffffffu, m, off));
    float s = __expf(a0 - m) + (hi ? __expf(a1 - m) : 0.f);
    #pragma unroll
    for (int off = 16; off > 0; off >>= 1)
        s += __shfl_xor_sync(0xffffffffu, s, off);
    float lse = m + __logf(s);

    float* o = out + (size_t)node * NC;
    o[lane] = a0 - lse;
    if (hi) o[32 + lane] = a1 - lse;
}

// ---------------- launcher ----------------
extern "C" void kernel_launch(void* const* d_in, const int* in_sizes, int n_in,
                              void* d_out, int out_size) {
    const float* x  = (const float*)d_in[0];
    const void*  ei = d_in[1];
    const float* ew = (const float*)d_in[2];
    const float* W1 = (const float*)d_in[3];
    const float* b1 = (const float*)d_in[4];
    const float* W2 = (const float*)d_in[5];
    const float* b2 = (const float*)d_in[6];
    float* out = (float*)d_out;

    const int EB = (NE + 255) / 256;
    const int GB = (NN + 63) / 64;
    const int AB = (NN * 32 + 255) / 256;

    void *p_cnt = nullptr, *p_degw = nullptr;
    cudaGetSymbolAddress(&p_cnt,  g_cnt);
    cudaGetSymbolAddress(&p_degw, g_degw);
    cudaMemsetAsync(p_cnt,  0, NN * sizeof(int));   // #1
    cudaMemsetAsync(p_degw, 0, NN * sizeof(float)); // #2

    k_detect<<<1, 256>>>((const long long*)ei);     // #3
    k_decode_deg<<<EB, 256>>>(ei, ew);              // #4
    k_scan1<<<NBLK, SCAN_B>>>();                    // #5
    k_gemm1<<<GB, 256>>>(x, W1);                    // #6  <- ncu -s 5 lands here
    k_scan2<<<1, 128>>>();                          // #7
    k_scan3<<<NBLK, SCAN_B>>>();                    // #8
    k_fill<<<EB, 256>>>(ew);                        // #9
    k_agg1<<<AB, 256>>>(b1);                        // #10
    k_gemm2<<<GB, 256>>>(W2);                       // #11
    k_agg2<<<AB, 256>>>(b2, out);                   // #12
}

// round 5
// speedup vs baseline: 1.4177x; 1.4177x over previous
#include <cuda_runtime.h>
#include <cuda_fp16.h>
#include <cuda_bf16.h>

#define NN 100000
#define NE 1600000
#define NF 128
#define NH 64
#define NC 40

#define SCAN_B 1024
#define NBLK ((NN + SCAN_B - 1) / SCAN_B)   // 98

#define AS_STRIDE (NH + 4)
#define WT_STRIDE (NH + 4)

#define GR 256        // rows per gemm1 block
#define APAD 136      // bf16 row stride in smem (272B: conflict-free frags)
#define G1_SMEM ((GR + NH) * APAD * 2)   // (256+64)*136*2 = 87040 B

// ---------------- scratch ----------------
__device__ int     g_is64;
__device__ int     g_src[NE];
__device__ int     g_dst[NE];
__device__ float   g_degw[NN];
__device__ int     g_cnt[NN];
__device__ int     g_rowptr[NN];
__device__ int     g_fill[NN];
__device__ float   g_dinv[NN];
__device__ int2    g_edge[NE];          // CSR: {src, float_bits(norm)}
__device__ __half2 g_h1h[NN * 32];      // h1 in fp16, 32 half2 per row
__device__ float   g_a1[NN * NH];
__device__ float   g_h2[NN * NC];
__device__ int     g_bsum[NBLK];

// ---------------- dtype detection ----------------
__global__ void k_detect(const long long* __restrict__ ei) {
    __shared__ int ok;
    if (threadIdx.x == 0) ok = 1;
    __syncthreads();
    long long v = ei[threadIdx.x];
    if (!(v >= 0 && v < (long long)NN)) atomicAnd(&ok, 0);
    __syncthreads();
    if (threadIdx.x == 0) g_is64 = ok;
}

// ---------------- fused decode + degree/count ----------------
__global__ void k_decode_deg(const void* __restrict__ ei, const float* __restrict__ w) {
    int e = blockIdx.x * blockDim.x + threadIdx.x;
    if (e >= NE) return;
    int s, d;
    if (g_is64) {
        const long long* p = (const long long*)ei;
        s = (int)p[e]; d = (int)p[NE + e];
    } else {
        const int* p = (const int*)ei;
        s = p[e]; d = p[NE + e];
    }
    g_src[e] = s;
    g_dst[e] = d;
    atomicAdd(&g_degw[d], w[e]);
    atomicAdd(&g_cnt[d], 1);
}

// ---------------- scan ----------------
__global__ void k_scan1() {
    __shared__ int s[SCAN_B];
    int gid = blockIdx.x * SCAN_B + threadIdx.x;
    int v = (gid < NN) ? g_cnt[gid] : 0;
    s[threadIdx.x] = v;
    __syncthreads();
    for (int off = 1; off < SCAN_B; off <<= 1) {
        int t = (threadIdx.x >= off) ? s[threadIdx.x - off] : 0;
        __syncthreads();
        s[threadIdx.x] += t;
        __syncthreads();
    }
    int incl = s[threadIdx.x];
    if (gid < NN) g_rowptr[gid] = incl - v;
    if (threadIdx.x == SCAN_B - 1) g_bsum[blockIdx.x] = incl;
}

__global__ void k_scan2() {
    __shared__ int s[128];
    int t = threadIdx.x;
    int v = (t < NBLK) ? g_bsum[t] : 0;
    s[t] = v;
    __syncthreads();
    #pragma unroll
    for (int off = 1; off < 128; off <<= 1) {
        int u = (t >= off) ? s[t - off] : 0;
        __syncthreads();
        s[t] += u;
        __syncthreads();
    }
    if (t < NBLK) g_bsum[t] = s[t] - v;   // exclusive
}

__global__ void k_scan3() {
    int gid = blockIdx.x * SCAN_B + threadIdx.x;
    if (gid >= NN) return;
    int rp = g_rowptr[gid] + g_bsum[blockIdx.x];
    g_rowptr[gid] = rp;
    g_fill[gid]   = rp;
    g_dinv[gid]   = rsqrtf(g_degw[gid] + 1.0f);
}

// ---------------- CSR fill ----------------
__global__ void k_fill(const float* __restrict__ w) {
    int e = blockIdx.x * blockDim.x + threadIdx.x;
    if (e >= NE) return;
    int s = g_src[e], d = g_dst[e];
    int pos = atomicAdd(&g_fill[d], 1);
    float nv = g_dinv[s] * w[e] * g_dinv[d];
    g_edge[pos] = make_int2(s, __float_as_int(nv));
}

// ---------------- GEMM1: h1 = x @ W1 via bf16 mma.sync, fp16 output ----------------
__device__ __forceinline__ void mma16816(float* d,
                                         unsigned a0, unsigned a1, unsigned a2, unsigned a3,
                                         unsigned b0, unsigned b1) {
    asm volatile(
        "mma.sync.aligned.m16n8k16.row.col.f32.bf16.bf16.f32 "
        "{%0,%1,%2,%3}, {%4,%5,%6,%7}, {%8,%9}, {%0,%1,%2,%3};"
        : "+f"(d[0]), "+f"(d[1]), "+f"(d[2]), "+f"(d[3])
        : "r"(a0), "r"(a1), "r"(a2), "r"(a3), "r"(b0), "r"(b1));
}

__global__ __launch_bounds__(256) void k_gemm1(const float* __restrict__ x,
                                               const float* __restrict__ W1) {
    extern __shared__ __nv_bfloat16 sh[];
    __nv_bfloat16* As = sh;                  // [GR][APAD]
    __nv_bfloat16* Ws = sh + GR * APAD;      // [NH][APAD]  (W transposed: [n][k])
    int tid = threadIdx.x;
    int row0 = blockIdx.x * GR;

    // W1 [k][n] fp32 -> Ws[n][k] bf16
    const float4* W4 = (const float4*)W1;
    for (int i = tid; i < (NF * NH) / 4; i += 256) {
        int idx = i * 4;
        int k = idx / NH;
        int n = idx % NH;
        float4 w = W4[i];
        Ws[(n + 0) * APAD + k] = __float2bfloat16(w.x);
        Ws[(n + 1) * APAD + k] = __float2bfloat16(w.y);
        Ws[(n + 2) * APAD + k] = __float2bfloat16(w.z);
        Ws[(n + 3) * APAD + k] = __float2bfloat16(w.w);
    }

    // x rows -> As bf16 (one full row per warp per iteration; fully coalesced LDG)
    const float4* x4 = (const float4*)x;
    #pragma unroll
    for (int it = 0; it < GR * 32 / 256; it++) {   // 32 iters
        int i  = tid + 256 * it;       // float4 index within tile
        int r  = i >> 5;               // local row
        int c4 = i & 31;               // float4 within row
        int gr = row0 + r;
        float4 v = (gr < NN) ? x4[(size_t)gr * 32 + c4] : make_float4(0.f, 0.f, 0.f, 0.f);
        __nv_bfloat162 p0 = __float22bfloat162_rn(make_float2(v.x, v.y));
        __nv_bfloat162 p1 = __float22bfloat162_rn(make_float2(v.z, v.w));
        *(__nv_bfloat162*)&As[r * APAD + c4 * 4]     = p0;
        *(__nv_bfloat162*)&As[r * APAD + c4 * 4 + 2] = p1;
    }
    __syncthreads();

    int w    = tid >> 5;
    int lane = tid & 31;
    int g    = lane >> 2;
    int tg   = lane & 3;
    int mrow0 = w * 32;                 // local row base for this warp

    float acc[2][8][4];
    #pragma unroll
    for (int mt = 0; mt < 2; mt++)
        #pragma unroll
        for (int nt = 0; nt < 8; nt++)
            #pragma unroll
            for (int c = 0; c < 4; c++) acc[mt][nt][c] = 0.f;

    #pragma unroll
    for (int ks = 0; ks < NF / 16; ks++) {
        int k0 = ks * 16;
        unsigned a[2][4];
        #pragma unroll
        for (int mt = 0; mt < 2; mt++) {
            int rb = mrow0 + mt * 16;
            a[mt][0] = *(const unsigned*)&As[(rb + g)     * APAD + k0 + tg * 2];
            a[mt][1] = *(const unsigned*)&As[(rb + g + 8) * APAD + k0 + tg * 2];
            a[mt][2] = *(const unsigned*)&As[(rb + g)     * APAD + k0 + tg * 2 + 8];
            a[mt][3] = *(const unsigned*)&As[(rb + g + 8) * APAD + k0 + tg * 2 + 8];
        }
        #pragma unroll
        for (int nt = 0; nt < 8; nt++) {
            unsigned b0 = *(const unsigned*)&Ws[(nt * 8 + g) * APAD + k0 + tg * 2];
            unsigned b1 = *(const unsigned*)&Ws[(nt * 8 + g) * APAD + k0 + tg * 2 + 8];
            mma16816(acc[0][nt], a[0][0], a[0][1], a[0][2], a[0][3], b0, b1);
            mma16816(acc[1][nt], a[1][0], a[1][1], a[1][2], a[1][3], b0, b1);
        }
    }

    // store C fragments -> g_h1h fp16
    #pragma unroll
    for (int mt = 0; mt < 2; mt++) {
        int rA = row0 + mrow0 + mt * 16 + g;       // rows g and g+8
        int rB = rA + 8;
        #pragma unroll
        for (int nt = 0; nt < 8; nt++) {
            int colh2 = nt * 4 + tg;               // half2 column index
            if (rA < NN)
                g_h1h[(size_t)rA * 32 + colh2] =
                    __floats2half2_rn(acc[mt][nt][0], acc[mt][nt][1]);
            if (rB < NN)
                g_h1h[(size_t)rB * 32 + colh2] =
                    __floats2half2_rn(acc[mt][nt][2], acc[mt][nt][3]);
        }
    }
}

// ---------------- AGG1: fp16 gather + bias + relu -> a1 (fp32) ----------------
__global__ __launch_bounds__(256) void k_agg1(const float* __restrict__ b1) {
    int node = (blockIdx.x * blockDim.x + threadIdx.x) >> 5;
    int lane = threadIdx.x & 31;
    if (node >= NN) return;
    int beg = g_rowptr[node];
    int end = beg + g_cnt[node];
    float di = g_dinv[node];
    float self = di * di;
    float2 hf = __half22float2(g_h1h[(size_t)node * 32 + lane]);
    float a0 = self * hf.x;
    float a1 = self * hf.y;

    int e = beg;
    for (; e + 3 < end; e += 4) {
        int2 e0 = g_edge[e],     e1 = g_edge[e + 1];
        int2 e2 = g_edge[e + 2], e3 = g_edge[e + 3];
        __half2 v0 = g_h1h[(size_t)e0.x * 32 + lane];
        __half2 v1 = g_h1h[(size_t)e1.x * 32 + lane];
        __half2 v2 = g_h1h[(size_t)e2.x * 32 + lane];
        __half2 v3 = g_h1h[(size_t)e3.x * 32 + lane];
        float n0 = __int_as_float(e0.y), n1 = __int_as_float(e1.y);
        float n2 = __int_as_float(e2.y), n3 = __int_as_float(e3.y);
        float2 f0 = __half22float2(v0), f1 = __half22float2(v1);
        float2 f2 = __half22float2(v2), f3 = __half22float2(v3);
        a0 = fmaf(n0, f0.x, a0); a1 = fmaf(n0, f0.y, a1);
        a0 = fmaf(n1, f1.x, a0); a1 = fmaf(n1, f1.y, a1);
        a0 = fmaf(n2, f2.x, a0); a1 = fmaf(n2, f2.y, a1);
        a0 = fmaf(n3, f3.x, a0); a1 = fmaf(n3, f3.y, a1);
    }
    for (; e < end; e++) {
        int2 ed = g_edge[e];
        float n = __int_as_float(ed.y);
        float2 f = __half22float2(g_h1h[(size_t)ed.x * 32 + lane]);
        a0 = fmaf(n, f.x, a0); a1 = fmaf(n, f.y, a1);
    }
    float2 bb = *(const float2*)&b1[2 * lane];
    a0 += bb.x;
    a1 += bb.y;
    float2 st = make_float2(fmaxf(a0, 0.f), fmaxf(a1, 0.f));
    *(float2*)&g_a1[(size_t)node * NH + 2 * lane] = st;
}

// ---------------- GEMM2: h2 = a1 @ W2 ----------------
__global__ __launch_bounds__(256) void k_gemm2(const float* __restrict__ W2) {
    __shared__ float WsT[NC * WT_STRIDE];
    __shared__ float as[64 * AS_STRIDE];
    int tid = threadIdx.x;
    int row0 = blockIdx.x * 64;

    for (int i = tid; i < NH * NC; i += 256) {
        int k = i / NC, c = i % NC;
        WsT[c * WT_STRIDE + k] = W2[i];
    }
    const float4* a4 = (const float4*)g_a1 + row0 * (NH / 4);
    int limit4 = (NN - row0) * (NH / 4);
    for (int i = tid; i < 64 * (NH / 4); i += 256) {
        int rr = i >> 4;
        int cc = i & 15;
        float4 v = (i < limit4) ? a4[i] : make_float4(0.f, 0.f, 0.f, 0.f);
        *(float4*)&as[rr * AS_STRIDE + cc * 4] = v;
    }
    __syncthreads();

    int r  = tid >> 3;
    int cg = tid & 7;
    float acc0[5] = {0, 0, 0, 0, 0};
    float acc1[5] = {0, 0, 0, 0, 0};
    const float* ar0 = &as[r * AS_STRIDE];
    const float* ar1 = &as[(r + 32) * AS_STRIDE];
    #pragma unroll
    for (int kk = 0; kk < NH / 4; kk++) {
        float4 av0 = *(const float4*)&ar0[kk * 4];
        float4 av1 = *(const float4*)&ar1[kk * 4];
        #pragma unroll
        for (int j = 0; j < 5; j++) {
            float4 w = *(const float4*)&WsT[(cg * 5 + j) * WT_STRIDE + kk * 4];
            acc0[j] += av0.x * w.x + av0.y * w.y + av0.z * w.z + av0.w * w.w;
            acc1[j] += av1.x * w.x + av1.y * w.y + av1.z * w.z + av1.w * w.w;
        }
    }
    int r0g = row0 + r, r1g = row0 + r + 32;
    if (r0g < NN) {
        float* o = g_h2 + (size_t)r0g * NC + cg * 5;
        #pragma unroll
        for (int j = 0; j < 5; j++) o[j] = acc0[j];
    }
    if (r1g < NN) {
        float* o = g_h2 + (size_t)r1g * NC + cg * 5;
        #pragma unroll
        for (int j = 0; j < 5; j++) o[j] = acc1[j];
    }
}

// ---------------- AGG2 + bias + log_softmax ----------------
__global__ __launch_bounds__(256) void k_agg2(const float* __restrict__ b2,
                                              float* __restrict__ out) {
    int node = (blockIdx.x * blockDim.x + threadIdx.x) >> 5;
    int lane = threadIdx.x & 31;
    if (node >= NN) return;
    bool hi = (lane < NC - 32);
    int beg = g_rowptr[node];
    int end = beg + g_cnt[node];
    float di = g_dinv[node];
    float self = di * di;
    const float* hn = &g_h2[(size_t)node * NC];
    float a0 = self * hn[lane];
    float a1 = hi ? self * hn[32 + lane] : 0.f;

    int e = beg;
    for (; e + 3 < end; e += 4) {
        int2 e0 = g_edge[e],     e1 = g_edge[e + 1];
        int2 e2 = g_edge[e + 2], e3 = g_edge[e + 3];
        const float* p0 = &g_h2[(size_t)e0.x * NC];
        const float* p1 = &g_h2[(size_t)e1.x * NC];
        const float* p2 = &g_h2[(size_t)e2.x * NC];
        const float* p3 = &g_h2[(size_t)e3.x * NC];
        float n0 = __int_as_float(e0.y), n1 = __int_as_float(e1.y);
        float n2 = __int_as_float(e2.y), n3 = __int_as_float(e3.y);
        float v0 = p0[lane], v1 = p1[lane], v2 = p2[lane], v3 = p3[lane];
        a0 = fmaf(n0, v0, a0); a0 = fmaf(n1, v1, a0);
        a0 = fmaf(n2, v2, a0); a0 = fmaf(n3, v3, a0);
        if (hi) {
            float u0 = p0[32 + lane], u1 = p1[32 + lane];
            float u2 = p2[32 + lane], u3 = p3[32 + lane];
            a1 = fmaf(n0, u0, a1); a1 = fmaf(n1, u1, a1);
            a1 = fmaf(n2, u2, a1); a1 = fmaf(n3, u3, a1);
        }
    }
    for (; e < end; e++) {
        int2 ed = g_edge[e];
        const float* p = &g_h2[(size_t)ed.x * NC];
        float n = __int_as_float(ed.y);
        a0 = fmaf(n, p[lane], a0);
        if (hi) a1 = fmaf(n, p[32 + lane], a1);
    }
    a0 += b2[lane];
    if (hi) a1 += b2[32 + lane];

    float m = hi ? fmaxf(a0, a1) : a0;
    #pragma unroll
    for (int off = 16; off > 0; off >>= 1)
        m = fmaxf(m, __shfl_xor_sync(0xffffffffu, m, off));
    float s = __expf(a0 - m) + (hi ? __expf(a1 - m) : 0.f);
    #pragma unroll
    for (int off = 16; off > 0; off >>= 1)
        s += __shfl_xor_sync(0xffffffffu, s, off);
    float lse = m + __logf(s);

    float* o = out + (size_t)node * NC;
    o[lane] = a0 - lse;
    if (hi) o[32 + lane] = a1 - lse;
}

// ---------------- launcher ----------------
extern "C" void kernel_launch(void* const* d_in, const int* in_sizes, int n_in,
                              void* d_out, int out_size) {
    const float* x  = (const float*)d_in[0];
    const void*  ei = d_in[1];
    const float* ew = (const float*)d_in[2];
    const float* W1 = (const float*)d_in[3];
    const float* b1 = (const float*)d_in[4];
    const float* W2 = (const float*)d_in[5];
    const float* b2 = (const float*)d_in[6];
    float* out = (float*)d_out;

    const int EB  = (NE + 255) / 256;
    const int G1B = (NN + GR - 1) / GR;     // 391
    const int G2B = (NN + 63) / 64;
    const int AB  = (NN * 32 + 255) / 256;

    cudaFuncSetAttribute(k_gemm1, cudaFuncAttributeMaxDynamicSharedMemorySize, G1_SMEM);

    void *p_cnt = nullptr, *p_degw = nullptr;
    cudaGetSymbolAddress(&p_cnt,  g_cnt);
    cudaGetSymbolAddress(&p_degw, g_degw);
    cudaMemsetAsync(p_cnt,  0, NN * sizeof(int));   // #1
    cudaMemsetAsync(p_degw, 0, NN * sizeof(float)); // #2

    k_detect<<<1, 256>>>((const long long*)ei);     // #3
    k_decode_deg<<<EB, 256>>>(ei, ew);              // #4
    k_scan1<<<NBLK, SCAN_B>>>();                    // #5
    k_gemm1<<<G1B, 256, G1_SMEM>>>(x, W1);          // #6  <- ncu -s 5 lands here
    k_scan2<<<1, 128>>>();                          // #7
    k_scan3<<<NBLK, SCAN_B>>>();                    // #8
    k_fill<<<EB, 256>>>(ew);                        // #9
    k_agg1<<<AB, 256>>>(b1);                        // #10
    k_gemm2<<<G2B, 256>>>(W2);                      // #11
    k_agg2<<<AB, 256>>>(b2, out);                   // #12
}

// round 6
// speedup vs baseline: 1.4552x; 1.0265x over previous
#include <cuda_runtime.h>
#include <cuda_fp16.h>
#include <cuda_bf16.h>

#define NN 100000
#define NE 1600000
#define NF 128
#define NH 64
#define NC 40

#define SCAN_B 1024
#define NBLK ((NN + SCAN_B - 1) / SCAN_B)   // 98

#define AS_STRIDE (NH + 4)
#define WT_STRIDE (NH + 4)

#define GR 128        // rows per gemm1 block
#define APAD 136      // bf16 row stride in smem (272B: conflict-free frags)
#define G1_SMEM ((GR + NH) * APAD * 2)   // (128+64)*136*2 = 52224 B

// ---------------- scratch ----------------
__device__ int     g_is64;
__device__ int     g_src[NE];
__device__ int     g_dst[NE];
__device__ float   g_degw[NN];
__device__ int     g_cnt[NN];
__device__ int     g_rowptr[NN];
__device__ int     g_fill[NN];
__device__ float   g_dinv[NN];
__device__ int2    g_edge[NE];          // CSR: {src, float_bits(norm)}
__device__ __half2 g_h1h[NN * 32];      // h1 fp16, 32 half2 per row (128 B)
__device__ float   g_a1[NN * NH];
__device__ __half  g_h2h[NN * NC];      // h2 fp16, 40 half per row (80 B)
__device__ int     g_bsum[NBLK];

// ---------------- init: zero degw/cnt + dtype detect ----------------
__global__ void k_init(const long long* __restrict__ ei) {
    int i = blockIdx.x * blockDim.x + threadIdx.x;
    if (i < NN) { g_degw[i] = 0.f; g_cnt[i] = 0; }
    if (blockIdx.x == 0) {
        __shared__ int ok;
        if (threadIdx.x == 0) ok = 1;
        __syncthreads();
        long long v = ei[threadIdx.x];   // 256 leading values
        if (!(v >= 0 && v < (long long)NN)) atomicAnd(&ok, 0);
        __syncthreads();
        if (threadIdx.x == 0) g_is64 = ok;
    }
}

// ---------------- fused decode + degree/count ----------------
__global__ void k_decode_deg(const void* __restrict__ ei, const float* __restrict__ w) {
    int e = blockIdx.x * blockDim.x + threadIdx.x;
    if (e >= NE) return;
    int s, d;
    if (g_is64) {
        const long long* p = (const long long*)ei;
        s = (int)p[e]; d = (int)p[NE + e];
    } else {
        const int* p = (const int*)ei;
        s = p[e]; d = p[NE + e];
    }
    g_src[e] = s;
    g_dst[e] = d;
    atomicAdd(&g_degw[d], w[e]);
    atomicAdd(&g_cnt[d], 1);
}

// ---------------- scan stage 1 ----------------
__global__ void k_scan1() {
    __shared__ int s[SCAN_B];
    int gid = blockIdx.x * SCAN_B + threadIdx.x;
    int v = (gid < NN) ? g_cnt[gid] : 0;
    s[threadIdx.x] = v;
    __syncthreads();
    for (int off = 1; off < SCAN_B; off <<= 1) {
        int t = (threadIdx.x >= off) ? s[threadIdx.x - off] : 0;
        __syncthreads();
        s[threadIdx.x] += t;
        __syncthreads();
    }
    int incl = s[threadIdx.x];
    if (gid < NN) g_rowptr[gid] = incl - v;
    if (threadIdx.x == SCAN_B - 1) g_bsum[blockIdx.x] = incl;
}

// ---------------- scan stage 2+3 fused (+dinv) ----------------
__global__ void k_scan23() {
    __shared__ int bs[128];
    int t = threadIdx.x;
    if (t < 128) bs[t] = (t < NBLK) ? g_bsum[t] : 0;
    __syncthreads();
    #pragma unroll
    for (int off = 1; off < 128; off <<= 1) {
        int u = (t < 128 && t >= off) ? bs[t - off] : 0;
        __syncthreads();
        if (t < 128) bs[t] += u;
        __syncthreads();
    }
    int add = (blockIdx.x == 0) ? 0 : bs[blockIdx.x - 1];
    int gid = blockIdx.x * SCAN_B + t;
    if (gid < NN) {
        int rp = g_rowptr[gid] + add;
        g_rowptr[gid] = rp;
        g_fill[gid]   = rp;
        g_dinv[gid]   = rsqrtf(g_degw[gid] + 1.0f);
    }
}

// ---------------- CSR fill ----------------
__global__ void k_fill(const float* __restrict__ w) {
    int e = blockIdx.x * blockDim.x + threadIdx.x;
    if (e >= NE) return;
    int s = g_src[e], d = g_dst[e];
    int pos = atomicAdd(&g_fill[d], 1);
    float nv = g_dinv[s] * w[e] * g_dinv[d];
    g_edge[pos] = make_int2(s, __float_as_int(nv));
}

// ---------------- GEMM1: h1 = x @ W1 via bf16 mma.sync, fp16 output ----------------
__device__ __forceinline__ void mma16816(float* d,
                                         unsigned a0, unsigned a1, unsigned a2, unsigned a3,
                                         unsigned b0, unsigned b1) {
    asm volatile(
        "mma.sync.aligned.m16n8k16.row.col.f32.bf16.bf16.f32 "
        "{%0,%1,%2,%3}, {%4,%5,%6,%7}, {%8,%9}, {%0,%1,%2,%3};"
        : "+f"(d[0]), "+f"(d[1]), "+f"(d[2]), "+f"(d[3])
        : "r"(a0), "r"(a1), "r"(a2), "r"(a3), "r"(b0), "r"(b1));
}

__global__ __launch_bounds__(256) void k_gemm1(const float* __restrict__ x,
                                               const float* __restrict__ W1) {
    extern __shared__ __nv_bfloat16 sh[];
    __nv_bfloat16* As = sh;                  // [GR][APAD]
    __nv_bfloat16* Ws = sh + GR * APAD;      // [NH][APAD]  (W transposed: [n][k])
    int tid = threadIdx.x;
    int row0 = blockIdx.x * GR;

    // W1 [k][n] fp32 -> Ws[n][k] bf16
    const float4* W4 = (const float4*)W1;
    for (int i = tid; i < (NF * NH) / 4; i += 256) {
        int idx = i * 4;
        int k = idx / NH;
        int n = idx % NH;
        float4 w = W4[i];
        Ws[(n + 0) * APAD + k] = __float2bfloat16(w.x);
        Ws[(n + 1) * APAD + k] = __float2bfloat16(w.y);
        Ws[(n + 2) * APAD + k] = __float2bfloat16(w.z);
        Ws[(n + 3) * APAD + k] = __float2bfloat16(w.w);
    }

    // x rows -> As bf16
    const float4* x4 = (const float4*)x;
    #pragma unroll
    for (int it = 0; it < GR * 32 / 256; it++) {   // 16 iters
        int i  = tid + 256 * it;       // float4 index within tile
        int r  = i >> 5;               // local row
        int c4 = i & 31;               // float4 within row
        int gr = row0 + r;
        float4 v = (gr < NN) ? x4[(size_t)gr * 32 + c4] : make_float4(0.f, 0.f, 0.f, 0.f);
        __nv_bfloat162 p0 = __float22bfloat162_rn(make_float2(v.x, v.y));
        __nv_bfloat162 p1 = __float22bfloat162_rn(make_float2(v.z, v.w));
        *(__nv_bfloat162*)&As[r * APAD + c4 * 4]     = p0;
        *(__nv_bfloat162*)&As[r * APAD + c4 * 4 + 2] = p1;
    }
    __syncthreads();

    int w    = tid >> 5;
    int lane = tid & 31;
    int g    = lane >> 2;
    int tg   = lane & 3;
    int mrow0 = w * 16;                 // 16 rows per warp, 8 warps = 128

    float acc[8][4];
    #pragma unroll
    for (int nt = 0; nt < 8; nt++)
        #pragma unroll
        for (int c = 0; c < 4; c++) acc[nt][c] = 0.f;

    #pragma unroll
    for (int ks = 0; ks < NF / 16; ks++) {
        int k0 = ks * 16;
        unsigned a0 = *(const unsigned*)&As[(mrow0 + g)     * APAD + k0 + tg * 2];
        unsigned a1 = *(const unsigned*)&As[(mrow0 + g + 8) * APAD + k0 + tg * 2];
        unsigned a2 = *(const unsigned*)&As[(mrow0 + g)     * APAD + k0 + tg * 2 + 8];
        unsigned a3 = *(const unsigned*)&As[(mrow0 + g + 8) * APAD + k0 + tg * 2 + 8];
        #pragma unroll
        for (int nt = 0; nt < 8; nt++) {
            unsigned b0 = *(const unsigned*)&Ws[(nt * 8 + g) * APAD + k0 + tg * 2];
            unsigned b1 = *(const unsigned*)&Ws[(nt * 8 + g) * APAD + k0 + tg * 2 + 8];
            mma16816(acc[nt], a0, a1, a2, a3, b0, b1);
        }
    }

    // store C fragments -> g_h1h fp16
    int rA = row0 + mrow0 + g;       // rows g and g+8
    int rB = rA + 8;
    #pragma unroll
    for (int nt = 0; nt < 8; nt++) {
        int colh2 = nt * 4 + tg;
        if (rA < NN)
            g_h1h[(size_t)rA * 32 + colh2] = __floats2half2_rn(acc[nt][0], acc[nt][1]);
        if (rB < NN)
            g_h1h[(size_t)rB * 32 + colh2] = __floats2half2_rn(acc[nt][2], acc[nt][3]);
    }
}

// ---------------- AGG1: fp16 gather + bias + relu -> a1 (fp32) ----------------
__global__ __launch_bounds__(256) void k_agg1(const float* __restrict__ b1) {
    int node = (blockIdx.x * blockDim.x + threadIdx.x) >> 5;
    int lane = threadIdx.x & 31;
    if (node >= NN) return;
    int beg = g_rowptr[node];
    int end = beg + g_cnt[node];
    float di = g_dinv[node];
    float self = di * di;
    float2 hf = __half22float2(g_h1h[(size_t)node * 32 + lane]);
    float a0 = self * hf.x;
    float a1 = self * hf.y;

    int e = beg;
    for (; e + 3 < end; e += 4) {
        int2 e0 = g_edge[e],     e1 = g_edge[e + 1];
        int2 e2 = g_edge[e + 2], e3 = g_edge[e + 3];
        __half2 v0 = g_h1h[(size_t)e0.x * 32 + lane];
        __half2 v1 = g_h1h[(size_t)e1.x * 32 + lane];
        __half2 v2 = g_h1h[(size_t)e2.x * 32 + lane];
        __half2 v3 = g_h1h[(size_t)e3.x * 32 + lane];
        float n0 = __int_as_float(e0.y), n1 = __int_as_float(e1.y);
        float n2 = __int_as_float(e2.y), n3 = __int_as_float(e3.y);
        float2 f0 = __half22float2(v0), f1 = __half22float2(v1);
        float2 f2 = __half22float2(v2), f3 = __half22float2(v3);
        a0 = fmaf(n0, f0.x, a0); a1 = fmaf(n0, f0.y, a1);
        a0 = fmaf(n1, f1.x, a0); a1 = fmaf(n1, f1.y, a1);
        a0 = fmaf(n2, f2.x, a0); a1 = fmaf(n2, f2.y, a1);
        a0 = fmaf(n3, f3.x, a0); a1 = fmaf(n3, f3.y, a1);
    }
    for (; e < end; e++) {
        int2 ed = g_edge[e];
        float n = __int_as_float(ed.y);
        float2 f = __half22float2(g_h1h[(size_t)ed.x * 32 + lane]);
        a0 = fmaf(n, f.x, a0); a1 = fmaf(n, f.y, a1);
    }
    float2 bb = *(const float2*)&b1[2 * lane];
    a0 += bb.x;
    a1 += bb.y;
    float2 st = make_float2(fmaxf(a0, 0.f), fmaxf(a1, 0.f));
    *(float2*)&g_a1[(size_t)node * NH + 2 * lane] = st;
}

// ---------------- GEMM2: h2 = a1 @ W2 (fp16 output) ----------------
__global__ __launch_bounds__(256) void k_gemm2(const float* __restrict__ W2) {
    __shared__ float WsT[NC * WT_STRIDE];
    __shared__ float as[64 * AS_STRIDE];
    int tid = threadIdx.x;
    int row0 = blockIdx.x * 64;

    for (int i = tid; i < NH * NC; i += 256) {
        int k = i / NC, c = i % NC;
        WsT[c * WT_STRIDE + k] = W2[i];
    }
    const float4* a4 = (const float4*)g_a1 + row0 * (NH / 4);
    int limit4 = (NN - row0) * (NH / 4);
    for (int i = tid; i < 64 * (NH / 4); i += 256) {
        int rr = i >> 4;
        int cc = i & 15;
        float4 v = (i < limit4) ? a4[i] : make_float4(0.f, 0.f, 0.f, 0.f);
        *(float4*)&as[rr * AS_STRIDE + cc * 4] = v;
    }
    __syncthreads();

    int r  = tid >> 3;
    int cg = tid & 7;
    float acc0[5] = {0, 0, 0, 0, 0};
    float acc1[5] = {0, 0, 0, 0, 0};
    const float* ar0 = &as[r * AS_STRIDE];
    const float* ar1 = &as[(r + 32) * AS_STRIDE];
    #pragma unroll
    for (int kk = 0; kk < NH / 4; kk++) {
        float4 av0 = *(const float4*)&ar0[kk * 4];
        float4 av1 = *(const float4*)&ar1[kk * 4];
        #pragma unroll
        for (int j = 0; j < 5; j++) {
            float4 w = *(const float4*)&WsT[(cg * 5 + j) * WT_STRIDE + kk * 4];
            acc0[j] += av0.x * w.x + av0.y * w.y + av0.z * w.z + av0.w * w.w;
            acc1[j] += av1.x * w.x + av1.y * w.y + av1.z * w.z + av1.w * w.w;
        }
    }
    int r0g = row0 + r, r1g = row0 + r + 32;
    if (r0g < NN) {
        __half* o = g_h2h + (size_t)r0g * NC + cg * 5;
        #pragma unroll
        for (int j = 0; j < 5; j++) o[j] = __float2half(acc0[j]);
    }
    if (r1g < NN) {
        __half* o = g_h2h + (size_t)r1g * NC + cg * 5;
        #pragma unroll
        for (int j = 0; j < 5; j++) o[j] = __float2half(acc1[j]);
    }
}

// ---------------- AGG2 (fp16 gather) + bias + log_softmax ----------------
__global__ __launch_bounds__(256) void k_agg2(const float* __restrict__ b2,
                                              float* __restrict__ out) {
    int node = (blockIdx.x * blockDim.x + threadIdx.x) >> 5;
    int lane = threadIdx.x & 31;
    if (node >= NN) return;
    bool hi = (lane < NC - 32);
    int beg = g_rowptr[node];
    int end = beg + g_cnt[node];
    float di = g_dinv[node];
    float self = di * di;
    const __half* hn = &g_h2h[(size_t)node * NC];
    float a0 = self * __half2float(hn[lane]);
    float a1 = hi ? self * __half2float(hn[32 + lane]) : 0.f;

    int e = beg;
    for (; e + 3 < end; e += 4) {
        int2 e0 = g_edge[e],     e1 = g_edge[e + 1];
        int2 e2 = g_edge[e + 2], e3 = g_edge[e + 3];
        const __half* p0 = &g_h2h[(size_t)e0.x * NC];
        const __half* p1 = &g_h2h[(size_t)e1.x * NC];
        const __half* p2 = &g_h2h[(size_t)e2.x * NC];
        const __half* p3 = &g_h2h[(size_t)e3.x * NC];
        float n0 = __int_as_float(e0.y), n1 = __int_as_float(e1.y);
        float n2 = __int_as_float(e2.y), n3 = __int_as_float(e3.y);
        float v0 = __half2float(p0[lane]), v1 = __half2float(p1[lane]);
        float v2 = __half2float(p2[lane]), v3 = __half2float(p3[lane]);
        a0 = fmaf(n0, v0, a0); a0 = fmaf(n1, v1, a0);
        a0 = fmaf(n2, v2, a0); a0 = fmaf(n3, v3, a0);
        if (hi) {
            float u0 = __half2float(p0[32 + lane]), u1 = __half2float(p1[32 + lane]);
            float u2 = __half2float(p2[32 + lane]), u3 = __half2float(p3[32 + lane]);
            a1 = fmaf(n0, u0, a1); a1 = fmaf(n1, u1, a1);
            a1 = fmaf(n2, u2, a1); a1 = fmaf(n3, u3, a1);
        }
    }
    for (; e < end; e++) {
        int2 ed = g_edge[e];
        const __half* p = &g_h2h[(size_t)ed.x * NC];
        float n = __int_as_float(ed.y);
        a0 = fmaf(n, __half2float(p[lane]), a0);
        if (hi) a1 = fmaf(n, __half2float(p[32 + lane]), a1);
    }
    a0 += b2[lane];
    if (hi) a1 += b2[32 + lane];

    float m = hi ? fmaxf(a0, a1) : a0;
    #pragma unroll
    for (int off = 16; off > 0; off >>= 1)
        m = fmaxf(m, __shfl_xor_sync(0xffffffffu, m, off));
    float s = __expf(a0 - m) + (hi ? __expf(a1 - m) : 0.f);
    #pragma unroll
    for (int off = 16; off > 0; off >>= 1)
        s += __shfl_xor_sync(0xffffffffu, s, off);
    float lse = m + __logf(s);

    float* o = out + (size_t)node * NC;
    o[lane] = a0 - lse;
    if (hi) o[32 + lane] = a1 - lse;
}

// ---------------- launcher ----------------
extern "C" void kernel_launch(void* const* d_in, const int* in_sizes, int n_in,
                              void* d_out, int out_size) {
    const float* x  = (const float*)d_in[0];
    const void*  ei = d_in[1];
    const float* ew = (const float*)d_in[2];
    const float* W1 = (const float*)d_in[3];
    const float* b1 = (const float*)d_in[4];
    const float* W2 = (const float*)d_in[5];
    const float* b2 = (const float*)d_in[6];
    float* out = (float*)d_out;

    const int EB  = (NE + 255) / 256;      // 6250
    const int VB  = (NN + 255) / 256;      // 391
    const int G1B = (NN + GR - 1) / GR;    // 782
    const int G2B = (NN + 63) / 64;
    const int AB  = (NN * 32 + 255) / 256;

    cudaFuncSetAttribute(k_gemm1, cudaFuncAttributeMaxDynamicSharedMemorySize, G1_SMEM);

    k_init<<<VB, 256>>>((const long long*)ei);      // 0
    k_decode_deg<<<EB, 256>>>(ei, ew);              // 1
    k_scan1<<<NBLK, SCAN_B>>>();                    // 2
    k_scan23<<<NBLK, SCAN_B>>>();                   // 3
    k_gemm1<<<G1B, 256, G1_SMEM>>>(x, W1);          // 4
    k_fill<<<EB, 256>>>(ew);                        // 5  <- ncu -s 5 lands here
    k_agg1<<<AB, 256>>>(b1);                        // 6
    k_gemm2<<<G2B, 256>>>(W2);                      // 7
    k_agg2<<<AB, 256>>>(b2, out);                   // 8
}

// round 7
// speedup vs baseline: 1.7218x; 1.1832x over previous
#include <cuda_runtime.h>
#include <cuda_fp16.h>
#include <cuda_bf16.h>

#define NN 100000
#define NE 1600000
#define NF 128
#define NH 64
#define NC 40

#define SCAN_B 1024
#define NBLK ((NN + SCAN_B - 1) / SCAN_B)   // 98

#define GR 256        // rows per gemm1 block (measured-best)
#define APAD 136      // bf16 row stride in smem
#define G1_SMEM ((GR + NH) * APAD * 2)   // (256+64)*136*2 = 87040 B

#define G2R 128       // rows per gemm2 block
#define A2PAD 72      // half row stride (144 B) — conflict-free frags
#define G2_SMEM ((G2R + NC) * A2PAD * 2) // (128+40)*72*2 = 24192 B

// ---------------- scratch ----------------
__device__ int                 g_is64;
__device__ int                 g_src[NE];
__device__ int                 g_dst[NE];
__device__ unsigned long long  g_pack[NN];   // (cnt<<40) | fixedpoint(sum w, 2^32)
__device__ int                 g_rowptr[NN];
__device__ int                 g_fill[NN];   // after k_fill: == row end
__device__ float               g_dinv[NN];
__device__ int2                g_edge[NE];   // CSR: {src, float_bits(norm)}
__device__ __half2             g_h1h[NN * 32];  // h1 fp16 (128 B rows)
__device__ __half2             g_a1h[NN * 32];  // a1 fp16 (128 B rows)
__device__ __half              g_h2h[NN * NC];  // h2 fp16 (80 B rows)
__device__ int                 g_bsum[NBLK];

// ---------------- init: zero pack + dtype detect ----------------
__global__ void k_init(const long long* __restrict__ ei) {
    int i = blockIdx.x * blockDim.x + threadIdx.x;
    if (i < NN) g_pack[i] = 0ull;
    if (blockIdx.x == 0) {
        __shared__ int ok;
        if (threadIdx.x == 0) ok = 1;
        __syncthreads();
        long long v = ei[threadIdx.x];   // 256 leading values
        if (!(v >= 0 && v < (long long)NN)) atomicAnd(&ok, 0);
        __syncthreads();
        if (threadIdx.x == 0) g_is64 = ok;
    }
}

// ---------------- fused decode + packed degree/count ----------------
__global__ void k_decode_deg(const void* __restrict__ ei, const float* __restrict__ w) {
    int e = blockIdx.x * blockDim.x + threadIdx.x;
    if (e >= NE) return;
    int s, d;
    if (g_is64) {
        const long long* p = (const long long*)ei;
        s = (int)p[e]; d = (int)p[NE + e];
    } else {
        const int* p = (const int*)ei;
        s = p[e]; d = p[NE + e];
    }
    g_src[e] = s;
    g_dst[e] = d;
    unsigned long long add = (1ull << 40) |
        (unsigned long long)(w[e] * 4294967296.0f);
    atomicAdd(&g_pack[d], add);
}

// ---------------- scan stage 1 (counts from packed word) ----------------
__global__ void k_scan1() {
    __shared__ int s[SCAN_B];
    int gid = blockIdx.x * SCAN_B + threadIdx.x;
    int v = (gid < NN) ? (int)(g_pack[gid] >> 40) : 0;
    s[threadIdx.x] = v;
    __syncthreads();
    for (int off = 1; off < SCAN_B; off <<= 1) {
        int t = (threadIdx.x >= off) ? s[threadIdx.x - off] : 0;
        __syncthreads();
        s[threadIdx.x] += t;
        __syncthreads();
    }
    int incl = s[threadIdx.x];
    if (gid < NN) g_rowptr[gid] = incl - v;
    if (threadIdx.x == SCAN_B - 1) g_bsum[blockIdx.x] = incl;
}

// ---------------- scan stage 2+3 fused (+dinv) ----------------
__global__ void k_scan23() {
    __shared__ int bs[128];
    int t = threadIdx.x;
    if (t < 128) bs[t] = (t < NBLK) ? g_bsum[t] : 0;
    __syncthreads();
    #pragma unroll
    for (int off = 1; off < 128; off <<= 1) {
        int u = (t < 128 && t >= off) ? bs[t - off] : 0;
        __syncthreads();
        if (t < 128) bs[t] += u;
        __syncthreads();
    }
    int add = (blockIdx.x == 0) ? 0 : bs[blockIdx.x - 1];
    int gid = blockIdx.x * SCAN_B + t;
    if (gid < NN) {
        int rp = g_rowptr[gid] + add;
        g_rowptr[gid] = rp;
        g_fill[gid]   = rp;
        float degw = (float)(g_pack[gid] & 0xFFFFFFFFFFull) * (1.0f / 4294967296.0f);
        g_dinv[gid] = rsqrtf(degw + 1.0f);
    }
}

// ---------------- CSR fill ----------------
__global__ void k_fill(const float* __restrict__ w) {
    int e = blockIdx.x * blockDim.x + threadIdx.x;
    if (e >= NE) return;
    int s = g_src[e], d = g_dst[e];
    int pos = atomicAdd(&g_fill[d], 1);
    float nv = g_dinv[s] * w[e] * g_dinv[d];
    g_edge[pos] = make_int2(s, __float_as_int(nv));
}

// ---------------- mma helpers ----------------
__device__ __forceinline__ void mma16816bf(float* d,
                                           unsigned a0, unsigned a1, unsigned a2, unsigned a3,
                                           unsigned b0, unsigned b1) {
    asm volatile(
        "mma.sync.aligned.m16n8k16.row.col.f32.bf16.bf16.f32 "
        "{%0,%1,%2,%3}, {%4,%5,%6,%7}, {%8,%9}, {%0,%1,%2,%3};"
        : "+f"(d[0]), "+f"(d[1]), "+f"(d[2]), "+f"(d[3])
        : "r"(a0), "r"(a1), "r"(a2), "r"(a3), "r"(b0), "r"(b1));
}
__device__ __forceinline__ void mma16816h(float* d,
                                          unsigned a0, unsigned a1, unsigned a2, unsigned a3,
                                          unsigned b0, unsigned b1) {
    asm volatile(
        "mma.sync.aligned.m16n8k16.row.col.f32.f16.f16.f32 "
        "{%0,%1,%2,%3}, {%4,%5,%6,%7}, {%8,%9}, {%0,%1,%2,%3};"
        : "+f"(d[0]), "+f"(d[1]), "+f"(d[2]), "+f"(d[3])
        : "r"(a0), "r"(a1), "r"(a2), "r"(a3), "r"(b0), "r"(b1));
}

// ---------------- GEMM1: h1 = x @ W1 via bf16 mma, fp16 output (GR=256) -------
__global__ __launch_bounds__(256) void k_gemm1(const float* __restrict__ x,
                                               const float* __restrict__ W1) {
    extern __shared__ __nv_bfloat16 sh[];
    __nv_bfloat16* As = sh;                  // [GR][APAD]
    __nv_bfloat16* Ws = sh + GR * APAD;      // [NH][APAD]  (W transposed: [n][k])
    int tid = threadIdx.x;
    int row0 = blockIdx.x * GR;

    const float4* W4 = (const float4*)W1;
    for (int i = tid; i < (NF * NH) / 4; i += 256) {
        int idx = i * 4;
        int k = idx / NH;
        int n = idx % NH;
        float4 w = W4[i];
        Ws[(n + 0) * APAD + k] = __float2bfloat16(w.x);
        Ws[(n + 1) * APAD + k] = __float2bfloat16(w.y);
        Ws[(n + 2) * APAD + k] = __float2bfloat16(w.z);
        Ws[(n + 3) * APAD + k] = __float2bfloat16(w.w);
    }

    const float4* x4 = (const float4*)x;
    #pragma unroll
    for (int it = 0; it < GR * 32 / 256; it++) {   // 32 iters
        int i  = tid + 256 * it;
        int r  = i >> 5;
        int c4 = i & 31;
        int gr = row0 + r;
        float4 v = (gr < NN) ? x4[(size_t)gr * 32 + c4] : make_float4(0.f, 0.f, 0.f, 0.f);
        __nv_bfloat162 p0 = __float22bfloat162_rn(make_float2(v.x, v.y));
        __nv_bfloat162 p1 = __float22bfloat162_rn(make_float2(v.z, v.w));
        *(__nv_bfloat162*)&As[r * APAD + c4 * 4]     = p0;
        *(__nv_bfloat162*)&As[r * APAD + c4 * 4 + 2] = p1;
    }
    __syncthreads();

    int w    = tid >> 5;
    int lane = tid & 31;
    int g    = lane >> 2;
    int tg   = lane & 3;
    int mrow0 = w * 32;

    float acc[2][8][4];
    #pragma unroll
    for (int mt = 0; mt < 2; mt++)
        #pragma unroll
        for (int nt = 0; nt < 8; nt++)
            #pragma unroll
            for (int c = 0; c < 4; c++) acc[mt][nt][c] = 0.f;

    #pragma unroll
    for (int ks = 0; ks < NF / 16; ks++) {
        int k0 = ks * 16;
        unsigned a[2][4];
        #pragma unroll
        for (int mt = 0; mt < 2; mt++) {
            int rb = mrow0 + mt * 16;
            a[mt][0] = *(const unsigned*)&As[(rb + g)     * APAD + k0 + tg * 2];
            a[mt][1] = *(const unsigned*)&As[(rb + g + 8) * APAD + k0 + tg * 2];
            a[mt][2] = *(const unsigned*)&As[(rb + g)     * APAD + k0 + tg * 2 + 8];
            a[mt][3] = *(const unsigned*)&As[(rb + g + 8) * APAD + k0 + tg * 2 + 8];
        }
        #pragma unroll
        for (int nt = 0; nt < 8; nt++) {
            unsigned b0 = *(const unsigned*)&Ws[(nt * 8 + g) * APAD + k0 + tg * 2];
            unsigned b1 = *(const unsigned*)&Ws[(nt * 8 + g) * APAD + k0 + tg * 2 + 8];
            mma16816bf(acc[0][nt], a[0][0], a[0][1], a[0][2], a[0][3], b0, b1);
            mma16816bf(acc[1][nt], a[1][0], a[1][1], a[1][2], a[1][3], b0, b1);
        }
    }

    #pragma unroll
    for (int mt = 0; mt < 2; mt++) {
        int rA = row0 + mrow0 + mt * 16 + g;
        int rB = rA + 8;
        #pragma unroll
        for (int nt = 0; nt < 8; nt++) {
            int colh2 = nt * 4 + tg;
            if (rA < NN)
                g_h1h[(size_t)rA * 32 + colh2] = __floats2half2_rn(acc[mt][nt][0], acc[mt][nt][1]);
            if (rB < NN)
                g_h1h[(size_t)rB * 32 + colh2] = __floats2half2_rn(acc[mt][nt][2], acc[mt][nt][3]);
        }
    }
}

// ---------------- AGG1: fp16 gather + bias + relu -> a1 (fp16) ----------------
__global__ __launch_bounds__(256) void k_agg1(const float* __restrict__ b1) {
    int node = (blockIdx.x * blockDim.x + threadIdx.x) >> 5;
    int lane = threadIdx.x & 31;
    if (node >= NN) return;
    int beg = g_rowptr[node];
    int end = g_fill[node];
    float di = g_dinv[node];
    float self = di * di;
    float2 hf = __half22float2(g_h1h[(size_t)node * 32 + lane]);
    float a0 = self * hf.x;
    float a1 = self * hf.y;

    int e = beg;
    for (; e + 3 < end; e += 4) {
        int2 e0 = g_edge[e],     e1 = g_edge[e + 1];
        int2 e2 = g_edge[e + 2], e3 = g_edge[e + 3];
        __half2 v0 = g_h1h[(size_t)e0.x * 32 + lane];
        __half2 v1 = g_h1h[(size_t)e1.x * 32 + lane];
        __half2 v2 = g_h1h[(size_t)e2.x * 32 + lane];
        __half2 v3 = g_h1h[(size_t)e3.x * 32 + lane];
        float n0 = __int_as_float(e0.y), n1 = __int_as_float(e1.y);
        float n2 = __int_as_float(e2.y), n3 = __int_as_float(e3.y);
        float2 f0 = __half22float2(v0), f1 = __half22float2(v1);
        float2 f2 = __half22float2(v2), f3 = __half22float2(v3);
        a0 = fmaf(n0, f0.x, a0); a1 = fmaf(n0, f0.y, a1);
        a0 = fmaf(n1, f1.x, a0); a1 = fmaf(n1, f1.y, a1);
        a0 = fmaf(n2, f2.x, a0); a1 = fmaf(n2, f2.y, a1);
        a0 = fmaf(n3, f3.x, a0); a1 = fmaf(n3, f3.y, a1);
    }
    for (; e < end; e++) {
        int2 ed = g_edge[e];
        float n = __int_as_float(ed.y);
        float2 f = __half22float2(g_h1h[(size_t)ed.x * 32 + lane]);
        a0 = fmaf(n, f.x, a0); a1 = fmaf(n, f.y, a1);
    }
    float2 bb = *(const float2*)&b1[2 * lane];
    a0 = fmaxf(a0 + bb.x, 0.f);
    a1 = fmaxf(a1 + bb.y, 0.f);
    g_a1h[(size_t)node * 32 + lane] = __floats2half2_rn(a0, a1);
}

// ---------------- GEMM2: h2 = a1 @ W2 via fp16 mma, fp16 output ----------------
__global__ __launch_bounds__(256) void k_gemm2(const float* __restrict__ W2) {
    extern __shared__ __half sh2[];
    __half* As = sh2;                    // [G2R][A2PAD]
    __half* Ws = sh2 + G2R * A2PAD;      // [NC][A2PAD]  (W2 transposed: [n][k])
    int tid = threadIdx.x;
    int row0 = blockIdx.x * G2R;

    // W2 [k][n] fp32 -> Ws[n][k] half
    for (int i = tid; i < NH * NC; i += 256) {
        int k = i / NC, n = i % NC;
        Ws[n * A2PAD + k] = __float2half(W2[i]);
    }

    // a1 rows (fp16, 128B) -> As
    const uint4* a4 = (const uint4*)g_a1h;   // 8 uint4 per row
    #pragma unroll
    for (int it = 0; it < G2R * 8 / 256; it++) {   // 4 iters
        int i = tid + 256 * it;
        int r = i >> 3;
        int c = i & 7;
        int gr = row0 + r;
        uint4 v = (gr < NN) ? a4[(size_t)gr * 8 + c] : make_uint4(0u, 0u, 0u, 0u);
        *(uint4*)&As[r * A2PAD + c * 8] = v;
    }
    __syncthreads();

    int w    = tid >> 5;
    int lane = tid & 31;
    int g    = lane >> 2;
    int tg   = lane & 3;
    int mrow0 = w * 16;          // 16 rows/warp × 8 warps = 128

    float acc[5][4];
    #pragma unroll
    for (int nt = 0; nt < 5; nt++)
        #pragma unroll
        for (int c = 0; c < 4; c++) acc[nt][c] = 0.f;

    #pragma unroll
    for (int ks = 0; ks < NH / 16; ks++) {   // 4 ksteps
        int k0 = ks * 16;
        unsigned a0 = *(const unsigned*)&As[(mrow0 + g)     * A2PAD + k0 + tg * 2];
        unsigned a1 = *(const unsigned*)&As[(mrow0 + g + 8) * A2PAD + k0 + tg * 2];
        unsigned a2 = *(const unsigned*)&As[(mrow0 + g)     * A2PAD + k0 + tg * 2 + 8];
        unsigned a3 = *(const unsigned*)&As[(mrow0 + g + 8) * A2PAD + k0 + tg * 2 + 8];
        #pragma unroll
        for (int nt = 0; nt < 5; nt++) {
            unsigned b0 = *(const unsigned*)&Ws[(nt * 8 + g) * A2PAD + k0 + tg * 2];
            unsigned b1 = *(const unsigned*)&Ws[(nt * 8 + g) * A2PAD + k0 + tg * 2 + 8];
            mma16816h(acc[nt], a0, a1, a2, a3, b0, b1);
        }
    }

    int rA = row0 + mrow0 + g;
    int rB = rA + 8;
    #pragma unroll
    for (int nt = 0; nt < 5; nt++) {
        int col = nt * 8 + tg * 2;
        if (rA < NN)
            *(__half2*)&g_h2h[(size_t)rA * NC + col] = __floats2half2_rn(acc[nt][0], acc[nt][1]);
        if (rB < NN)
            *(__half2*)&g_h2h[(size_t)rB * NC + col] = __floats2half2_rn(acc[nt][2], acc[nt][3]);
    }
}

// ---------------- AGG2 (fp16 gather) + bias + log_softmax ----------------
__global__ __launch_bounds__(256) void k_agg2(const float* __restrict__ b2,
                                              float* __restrict__ out) {
    int node = (blockIdx.x * blockDim.x + threadIdx.x) >> 5;
    int lane = threadIdx.x & 31;
    if (node >= NN) return;
    bool hi = (lane < NC - 32);
    int beg = g_rowptr[node];
    int end = g_fill[node];
    float di = g_dinv[node];
    float self = di * di;
    const __half* hn = &g_h2h[(size_t)node * NC];
    float a0 = self * __half2float(hn[lane]);
    float a1 = hi ? self * __half2float(hn[32 + lane]) : 0.f;

    int e = beg;
    for (; e + 3 < end; e += 4) {
        int2 e0 = g_edge[e],     e1 = g_edge[e + 1];
        int2 e2 = g_edge[e + 2], e3 = g_edge[e + 3];
        const __half* p0 = &g_h2h[(size_t)e0.x * NC];
        const __half* p1 = &g_h2h[(size_t)e1.x * NC];
        const __half* p2 = &g_h2h[(size_t)e2.x * NC];
        const __half* p3 = &g_h2h[(size_t)e3.x * NC];
        float n0 = __int_as_float(e0.y), n1 = __int_as_float(e1.y);
        float n2 = __int_as_float(e2.y), n3 = __int_as_float(e3.y);
        float v0 = __half2float(p0[lane]), v1 = __half2float(p1[lane]);
        float v2 = __half2float(p2[lane]), v3 = __half2float(p3[lane]);
        a0 = fmaf(n0, v0, a0); a0 = fmaf(n1, v1, a0);
        a0 = fmaf(n2, v2, a0); a0 = fmaf(n3, v3, a0);
        if (hi) {
            float u0 = __half2float(p0[32 + lane]), u1 = __half2float(p1[32 + lane]);
            float u2 = __half2float(p2[32 + lane]), u3 = __half2float(p3[32 + lane]);
            a1 = fmaf(n0, u0, a1); a1 = fmaf(n1, u1, a1);
            a1 = fmaf(n2, u2, a1); a1 = fmaf(n3, u3, a1);
        }
    }
    for (; e < end; e++) {
        int2 ed = g_edge[e];
        const __half* p = &g_h2h[(size_t)ed.x * NC];
        float n = __int_as_float(ed.y);
        a0 = fmaf(n, __half2float(p[lane]), a0);
        if (hi) a1 = fmaf(n, __half2float(p[32 + lane]), a1);
    }
    a0 += b2[lane];
    if (hi) a1 += b2[32 + lane];

    float m = hi ? fmaxf(a0, a1) : a0;
    #pragma unroll
    for (int off = 16; off > 0; off >>= 1)
        m = fmaxf(m, __shfl_xor_sync(0xffffffffu, m, off));
    float s = __expf(a0 - m) + (hi ? __expf(a1 - m) : 0.f);
    #pragma unroll
    for (int off = 16; off > 0; off >>= 1)
        s += __shfl_xor_sync(0xffffffffu, s, off);
    float lse = m + __logf(s);

    float* o = out + (size_t)node * NC;
    o[lane] = a0 - lse;
    if (hi) o[32 + lane] = a1 - lse;
}

// ---------------- launcher ----------------
extern "C" void kernel_launch(void* const* d_in, const int* in_sizes, int n_in,
                              void* d_out, int out_size) {
    const float* x  = (const float*)d_in[0];
    const void*  ei = d_in[1];
    const float* ew = (const float*)d_in[2];
    const float* W1 = (const float*)d_in[3];
    const float* b1 = (const float*)d_in[4];
    const float* W2 = (const float*)d_in[5];
    const float* b2 = (const float*)d_in[6];
    float* out = (float*)d_out;

    const int EB  = (NE + 255) / 256;       // 6250
    const int VB  = (NN + 255) / 256;       // 391
    const int G1B = (NN + GR - 1) / GR;     // 391
    const int G2B = (NN + G2R - 1) / G2R;   // 782
    const int AB  = (NN * 32 + 255) / 256;  // 12500

    cudaFuncSetAttribute(k_gemm1, cudaFuncAttributeMaxDynamicSharedMemorySize, G1_SMEM);
    cudaFuncSetAttribute(k_gemm2, cudaFuncAttributeMaxDynamicSharedMemorySize, G2_SMEM);

    k_init<<<VB, 256>>>((const long long*)ei);      // 0
    k_decode_deg<<<EB, 256>>>(ei, ew);              // 1
    k_scan1<<<NBLK, SCAN_B>>>();                    // 2
    k_scan23<<<NBLK, SCAN_B>>>();                   // 3
    k_gemm1<<<G1B, 256, G1_SMEM>>>(x, W1);          // 4
    k_fill<<<EB, 256>>>(ew);                        // 5
    k_agg1<<<AB, 256>>>(b1);                        // 6
    k_gemm2<<<G2B, 256, G2_SMEM>>>(W2);             // 7
    k_agg2<<<AB, 256>>>(b2, out);                   // 8
}

// round 8
// speedup vs baseline: 1.7476x; 1.0150x over previous
#include <cuda_runtime.h>
#include <cuda_fp16.h>
#include <cuda_bf16.h>

#define NN 100000
#define NE 1600000
#define NF 128
#define NH 64
#define NC 40

#define SCAN_B 1024
#define NBLK ((NN + SCAN_B - 1) / SCAN_B)   // 98

#define GR 256        // rows per gemm1 block (measured-best)
#define APAD 136      // bf16 row stride in smem
#define G1_SMEM ((GR + NH) * APAD * 2)   // 87040 B

#define G2R 128       // rows per gemm2 block
#define A2PAD 72      // half row stride (144 B)
#define G2_SMEM ((G2R + NC) * A2PAD * 2) // 24192 B

// ---------------- scratch ----------------
__device__ int                 g_is64;
__device__ int                 g_src[NE];
__device__ int                 g_dst[NE];
__device__ unsigned long long  g_pack[NN];   // (cnt<<40) | fixedpoint(sum w, 2^32)
__device__ int                 g_rowptr[NN];
__device__ int                 g_fill[NN];   // after k_fill: == row end
__device__ float               g_dinv[NN];
__device__ int2                g_edge[NE];   // CSR: {src, float_bits(norm)}
__device__ __half2             g_h1h[NN * 32];  // h1 fp16 (128 B rows)
__device__ __half2             g_a1h[NN * 32];  // a1 fp16 (128 B rows)
__device__ __half              g_h2h[NN * NC];  // h2 fp16 (80 B rows)
__device__ volatile unsigned long long g_sstat[NBLK];  // lookback: flag<<63 | aggregate

// ---------------- init: zero pack + scan status + dtype detect ----------------
__global__ void k_init(const long long* __restrict__ ei) {
    int i = blockIdx.x * blockDim.x + threadIdx.x;
    if (i < NN) g_pack[i] = 0ull;
    if (i < NBLK) g_sstat[i] = 0ull;
    if (blockIdx.x == 0) {
        __shared__ int ok;
        if (threadIdx.x == 0) ok = 1;
        __syncthreads();
        long long v = ei[threadIdx.x];   // 256 leading values
        if (!(v >= 0 && v < (long long)NN)) atomicAnd(&ok, 0);
        __syncthreads();
        if (threadIdx.x == 0) g_is64 = ok;
    }
}

// ---------------- fused decode + packed degree/count ----------------
__global__ void k_decode_deg(const void* __restrict__ ei, const float* __restrict__ w) {
    int e = blockIdx.x * blockDim.x + threadIdx.x;
    if (e >= NE) return;
    int s, d;
    if (g_is64) {
        const long long* p = (const long long*)ei;
        s = (int)p[e]; d = (int)p[NE + e];
    } else {
        const int* p = (const int*)ei;
        s = p[e]; d = p[NE + e];
    }
    g_src[e] = s;
    g_dst[e] = d;
    unsigned long long add = (1ull << 40) |
        (unsigned long long)(w[e] * 4294967296.0f);
    atomicAdd(&g_pack[d], add);
}

// ---------------- single-pass scan (decoupled lookback) + dinv ----------------
__global__ __launch_bounds__(SCAN_B) void k_scan() {
    int b = blockIdx.x, t = threadIdx.x;
    int gid = b * SCAN_B + t;
    int v = (gid < NN) ? (int)(g_pack[gid] >> 40) : 0;

    int lane = t & 31, wid = t >> 5;
    // warp-level inclusive scan
    int incl = v;
    #pragma unroll
    for (int o = 1; o < 32; o <<= 1) {
        int u = __shfl_up_sync(0xffffffffu, incl, o);
        if (lane >= o) incl += u;
    }
    __shared__ int ws[32];
    if (lane == 31) ws[wid] = incl;
    __syncthreads();
    if (wid == 0) {
        int s = ws[lane];
        #pragma unroll
        for (int o = 1; o < 32; o <<= 1) {
            int u = __shfl_up_sync(0xffffffffu, s, o);
            if (lane >= o) s += u;
        }
        ws[lane] = s;
    }
    __syncthreads();
    if (wid > 0) incl += ws[wid - 1];
    int total = ws[31];

    // publish this block's aggregate (flag in bit 63)
    if (t == 0)
        atomicExch((unsigned long long*)&g_sstat[b],
                   (1ull << 63) | (unsigned long long)total);

    // warp 0: sum aggregates of all predecessor blocks (all co-resident: 98 < 148 SMs)
    __shared__ int boff_s;
    if (wid == 0) {
        int run = 0;
        for (int i = lane; i < b; i += 32) {
            unsigned long long s;
            do { s = g_sstat[i]; } while (!(s >> 63));
            run += (int)(s & 0x7FFFFFFFFFFFFFFFull);
        }
        #pragma unroll
        for (int o = 16; o > 0; o >>= 1)
            run += __shfl_xor_sync(0xffffffffu, run, o);
        if (lane == 0) boff_s = run;
    }
    __syncthreads();

    if (gid < NN) {
        int rp = boff_s + incl - v;     // exclusive prefix
        g_rowptr[gid] = rp;
        g_fill[gid]   = rp;
        float degw = (float)(g_pack[gid] & 0xFFFFFFFFFFull) * (1.0f / 4294967296.0f);
        g_dinv[gid] = rsqrtf(degw + 1.0f);
    }
}

// ---------------- CSR fill ----------------
__global__ void k_fill(const float* __restrict__ w) {
    int e = blockIdx.x * blockDim.x + threadIdx.x;
    if (e >= NE) return;
    int s = g_src[e], d = g_dst[e];
    int pos = atomicAdd(&g_fill[d], 1);
    float nv = g_dinv[s] * w[e] * g_dinv[d];
    g_edge[pos] = make_int2(s, __float_as_int(nv));
}

// ---------------- mma helpers ----------------
__device__ __forceinline__ void mma16816bf(float* d,
                                           unsigned a0, unsigned a1, unsigned a2, unsigned a3,
                                           unsigned b0, unsigned b1) {
    asm volatile(
        "mma.sync.aligned.m16n8k16.row.col.f32.bf16.bf16.f32 "
        "{%0,%1,%2,%3}, {%4,%5,%6,%7}, {%8,%9}, {%0,%1,%2,%3};"
        : "+f"(d[0]), "+f"(d[1]), "+f"(d[2]), "+f"(d[3])
        : "r"(a0), "r"(a1), "r"(a2), "r"(a3), "r"(b0), "r"(b1));
}
__device__ __forceinline__ void mma16816h(float* d,
                                          unsigned a0, unsigned a1, unsigned a2, unsigned a3,
                                          unsigned b0, unsigned b1) {
    asm volatile(
        "mma.sync.aligned.m16n8k16.row.col.f32.f16.f16.f32 "
        "{%0,%1,%2,%3}, {%4,%5,%6,%7}, {%8,%9}, {%0,%1,%2,%3};"
        : "+f"(d[0]), "+f"(d[1]), "+f"(d[2]), "+f"(d[3])
        : "r"(a0), "r"(a1), "r"(a2), "r"(a3), "r"(b0), "r"(b1));
}

// ---------------- GEMM1: h1 = x @ W1 via bf16 mma, fp16 output (GR=256) -------
__global__ __launch_bounds__(256) void k_gemm1(const float* __restrict__ x,
                                               const float* __restrict__ W1) {
    extern __shared__ __nv_bfloat16 sh[];
    __nv_bfloat16* As = sh;                  // [GR][APAD]
    __nv_bfloat16* Ws = sh + GR * APAD;      // [NH][APAD]  (W transposed: [n][k])
    int tid = threadIdx.x;
    int row0 = blockIdx.x * GR;

    const float4* W4 = (const float4*)W1;
    for (int i = tid; i < (NF * NH) / 4; i += 256) {
        int idx = i * 4;
        int k = idx / NH;
        int n = idx % NH;
        float4 w = W4[i];
        Ws[(n + 0) * APAD + k] = __float2bfloat16(w.x);
        Ws[(n + 1) * APAD + k] = __float2bfloat16(w.y);
        Ws[(n + 2) * APAD + k] = __float2bfloat16(w.z);
        Ws[(n + 3) * APAD + k] = __float2bfloat16(w.w);
    }

    const float4* x4 = (const float4*)x;
    #pragma unroll
    for (int it = 0; it < GR * 32 / 256; it++) {   // 32 iters
        int i  = tid + 256 * it;
        int r  = i >> 5;
        int c4 = i & 31;
        int gr = row0 + r;
        float4 v = (gr < NN) ? x4[(size_t)gr * 32 + c4] : make_float4(0.f, 0.f, 0.f, 0.f);
        __nv_bfloat162 p0 = __float22bfloat162_rn(make_float2(v.x, v.y));
        __nv_bfloat162 p1 = __float22bfloat162_rn(make_float2(v.z, v.w));
        *(__nv_bfloat162*)&As[r * APAD + c4 * 4]     = p0;
        *(__nv_bfloat162*)&As[r * APAD + c4 * 4 + 2] = p1;
    }
    __syncthreads();

    int w    = tid >> 5;
    int lane = tid & 31;
    int g    = lane >> 2;
    int tg   = lane & 3;
    int mrow0 = w * 32;

    float acc[2][8][4];
    #pragma unroll
    for (int mt = 0; mt < 2; mt++)
        #pragma unroll
        for (int nt = 0; nt < 8; nt++)
            #pragma unroll
            for (int c = 0; c < 4; c++) acc[mt][nt][c] = 0.f;

    #pragma unroll
    for (int ks = 0; ks < NF / 16; ks++) {
        int k0 = ks * 16;
        unsigned a[2][4];
        #pragma unroll
        for (int mt = 0; mt < 2; mt++) {
            int rb = mrow0 + mt * 16;
            a[mt][0] = *(const unsigned*)&As[(rb + g)     * APAD + k0 + tg * 2];
            a[mt][1] = *(const unsigned*)&As[(rb + g + 8) * APAD + k0 + tg * 2];
            a[mt][2] = *(const unsigned*)&As[(rb + g)     * APAD + k0 + tg * 2 + 8];
            a[mt][3] = *(const unsigned*)&As[(rb + g + 8) * APAD + k0 + tg * 2 + 8];
        }
        #pragma unroll
        for (int nt = 0; nt < 8; nt++) {
            unsigned b0 = *(const unsigned*)&Ws[(nt * 8 + g) * APAD + k0 + tg * 2];
            unsigned b1 = *(const unsigned*)&Ws[(nt * 8 + g) * APAD + k0 + tg * 2 + 8];
            mma16816bf(acc[0][nt], a[0][0], a[0][1], a[0][2], a[0][3], b0, b1);
            mma16816bf(acc[1][nt], a[1][0], a[1][1], a[1][2], a[1][3], b0, b1);
        }
    }

    #pragma unroll
    for (int mt = 0; mt < 2; mt++) {
        int rA = row0 + mrow0 + mt * 16 + g;
        int rB = rA + 8;
        #pragma unroll
        for (int nt = 0; nt < 8; nt++) {
            int colh2 = nt * 4 + tg;
            if (rA < NN)
                g_h1h[(size_t)rA * 32 + colh2] = __floats2half2_rn(acc[mt][nt][0], acc[mt][nt][1]);
            if (rB < NN)
                g_h1h[(size_t)rB * 32 + colh2] = __floats2half2_rn(acc[mt][nt][2], acc[mt][nt][3]);
        }
    }
}

// ---------------- AGG1: fp16 gather (unroll 8) + bias + relu -> a1 fp16 --------
__global__ __launch_bounds__(256) void k_agg1(const float* __restrict__ b1) {
    int node = (blockIdx.x * blockDim.x + threadIdx.x) >> 5;
    int lane = threadIdx.x & 31;
    if (node >= NN) return;
    int beg = g_rowptr[node];
    int end = g_fill[node];
    float di = g_dinv[node];
    float self = di * di;
    float2 hf = __half22float2(g_h1h[(size_t)node * 32 + lane]);
    float a0 = self * hf.x;
    float a1 = self * hf.y;

    int e = beg;
    for (; e + 7 < end; e += 8) {
        int2 ed[8];
        __half2 v[8];
        #pragma unroll
        for (int j = 0; j < 8; j++) ed[j] = g_edge[e + j];
        #pragma unroll
        for (int j = 0; j < 8; j++) v[j] = g_h1h[(size_t)ed[j].x * 32 + lane];
        #pragma unroll
        for (int j = 0; j < 8; j++) {
            float n = __int_as_float(ed[j].y);
            float2 f = __half22float2(v[j]);
            a0 = fmaf(n, f.x, a0);
            a1 = fmaf(n, f.y, a1);
        }
    }
    for (; e + 3 < end; e += 4) {
        int2 ed[4];
        __half2 v[4];
        #pragma unroll
        for (int j = 0; j < 4; j++) ed[j] = g_edge[e + j];
        #pragma unroll
        for (int j = 0; j < 4; j++) v[j] = g_h1h[(size_t)ed[j].x * 32 + lane];
        #pragma unroll
        for (int j = 0; j < 4; j++) {
            float n = __int_as_float(ed[j].y);
            float2 f = __half22float2(v[j]);
            a0 = fmaf(n, f.x, a0);
            a1 = fmaf(n, f.y, a1);
        }
    }
    for (; e < end; e++) {
        int2 ed = g_edge[e];
        float n = __int_as_float(ed.y);
        float2 f = __half22float2(g_h1h[(size_t)ed.x * 32 + lane]);
        a0 = fmaf(n, f.x, a0);
        a1 = fmaf(n, f.y, a1);
    }
    float2 bb = *(const float2*)&b1[2 * lane];
    a0 = fmaxf(a0 + bb.x, 0.f);
    a1 = fmaxf(a1 + bb.y, 0.f);
    g_a1h[(size_t)node * 32 + lane] = __floats2half2_rn(a0, a1);
}

// ---------------- GEMM2: h2 = a1 @ W2 via fp16 mma, fp16 output ----------------
__global__ __launch_bounds__(256) void k_gemm2(const float* __restrict__ W2) {
    extern __shared__ __half sh2[];
    __half* As = sh2;                    // [G2R][A2PAD]
    __half* Ws = sh2 + G2R * A2PAD;      // [NC][A2PAD]
    int tid = threadIdx.x;
    int row0 = blockIdx.x * G2R;

    for (int i = tid; i < NH * NC; i += 256) {
        int k = i / NC, n = i % NC;
        Ws[n * A2PAD + k] = __float2half(W2[i]);
    }
    const uint4* a4 = (const uint4*)g_a1h;
    #pragma unroll
    for (int it = 0; it < G2R * 8 / 256; it++) {
        int i = tid + 256 * it;
        int r = i >> 3;
        int c = i & 7;
        int gr = row0 + r;
        uint4 v = (gr < NN) ? a4[(size_t)gr * 8 + c] : make_uint4(0u, 0u, 0u, 0u);
        *(uint4*)&As[r * A2PAD + c * 8] = v;
    }
    __syncthreads();

    int w    = tid >> 5;
    int lane = tid & 31;
    int g    = lane >> 2;
    int tg   = lane & 3;
    int mrow0 = w * 16;

    float acc[5][4];
    #pragma unroll
    for (int nt = 0; nt < 5; nt++)
        #pragma unroll
        for (int c = 0; c < 4; c++) acc[nt][c] = 0.f;

    #pragma unroll
    for (int ks = 0; ks < NH / 16; ks++) {
        int k0 = ks * 16;
        unsigned a0 = *(const unsigned*)&As[(mrow0 + g)     * A2PAD + k0 + tg * 2];
        unsigned a1 = *(const unsigned*)&As[(mrow0 + g + 8) * A2PAD + k0 + tg * 2];
        unsigned a2 = *(const unsigned*)&As[(mrow0 + g)     * A2PAD + k0 + tg * 2 + 8];
        unsigned a3 = *(const unsigned*)&As[(mrow0 + g + 8) * A2PAD + k0 + tg * 2 + 8];
        #pragma unroll
        for (int nt = 0; nt < 5; nt++) {
            unsigned b0 = *(const unsigned*)&Ws[(nt * 8 + g) * A2PAD + k0 + tg * 2];
            unsigned b1 = *(const unsigned*)&Ws[(nt * 8 + g) * A2PAD + k0 + tg * 2 + 8];
            mma16816h(acc[nt], a0, a1, a2, a3, b0, b1);
        }
    }

    int rA = row0 + mrow0 + g;
    int rB = rA + 8;
    #pragma unroll
    for (int nt = 0; nt < 5; nt++) {
        int col = nt * 8 + tg * 2;
        if (rA < NN)
            *(__half2*)&g_h2h[(size_t)rA * NC + col] = __floats2half2_rn(acc[nt][0], acc[nt][1]);
        if (rB < NN)
            *(__half2*)&g_h2h[(size_t)rB * NC + col] = __floats2half2_rn(acc[nt][2], acc[nt][3]);
    }
}

// ---------------- AGG2 (fp16 gather, unroll 8) + bias + log_softmax ------------
__global__ __launch_bounds__(256) void k_agg2(const float* __restrict__ b2,
                                              float* __restrict__ out) {
    int node = (blockIdx.x * blockDim.x + threadIdx.x) >> 5;
    int lane = threadIdx.x & 31;
    if (node >= NN) return;
    bool hi = (lane < NC - 32);
    int beg = g_rowptr[node];
    int end = g_fill[node];
    float di = g_dinv[node];
    float self = di * di;
    const __half* hn = &g_h2h[(size_t)node * NC];
    float a0 = self * __half2float(hn[lane]);
    float a1 = hi ? self * __half2float(hn[32 + lane]) : 0.f;

    int e = beg;
    for (; e + 7 < end; e += 8) {
        int2 ed[8];
        __half v[8], u[8];
        #pragma unroll
        for (int j = 0; j < 8; j++) ed[j] = g_edge[e + j];
        #pragma unroll
        for (int j = 0; j < 8; j++) {
            const __half* p = &g_h2h[(size_t)ed[j].x * NC];
            v[j] = p[lane];
            u[j] = hi ? p[32 + lane] : __half(0.f);
        }
        #pragma unroll
        for (int j = 0; j < 8; j++) {
            float n = __int_as_float(ed[j].y);
            a0 = fmaf(n, __half2float(v[j]), a0);
            if (hi) a1 = fmaf(n, __half2float(u[j]), a1);
        }
    }
    for (; e + 3 < end; e += 4) {
        int2 ed[4];
        __half v[4], u[4];
        #pragma unroll
        for (int j = 0; j < 4; j++) ed[j] = g_edge[e + j];
        #pragma unroll
        for (int j = 0; j < 4; j++) {
            const __half* p = &g_h2h[(size_t)ed[j].x * NC];
            v[j] = p[lane];
            u[j] = hi ? p[32 + lane] : __half(0.f);
        }
        #pragma unroll
        for (int j = 0; j < 4; j++) {
            float n = __int_as_float(ed[j].y);
            a0 = fmaf(n, __half2float(v[j]), a0);
            if (hi) a1 = fmaf(n, __half2float(u[j]), a1);
        }
    }
    for (; e < end; e++) {
        int2 ed = g_edge[e];
        const __half* p = &g_h2h[(size_t)ed.x * NC];
        float n = __int_as_float(ed.y);
        a0 = fmaf(n, __half2float(p[lane]), a0);
        if (hi) a1 = fmaf(n, __half2float(p[32 + lane]), a1);
    }
    a0 += b2[lane];
    if (hi) a1 += b2[32 + lane];

    float m = hi ? fmaxf(a0, a1) : a0;
    #pragma unroll
    for (int off = 16; off > 0; off >>= 1)
        m = fmaxf(m, __shfl_xor_sync(0xffffffffu, m, off));
    float s = __expf(a0 - m) + (hi ? __expf(a1 - m) : 0.f);
    #pragma unroll
    for (int off = 16; off > 0; off >>= 1)
        s += __shfl_xor_sync(0xffffffffu, s, off);
    float lse = m + __logf(s);

    float* o = out + (size_t)node * NC;
    o[lane] = a0 - lse;
    if (hi) o[32 + lane] = a1 - lse;
}

// ---------------- launcher ----------------
extern "C" void kernel_launch(void* const* d_in, const int* in_sizes, int n_in,
                              void* d_out, int out_size) {
    const float* x  = (const float*)d_in[0];
    const void*  ei = d_in[1];
    const float* ew = (const float*)d_in[2];
    const float* W1 = (const float*)d_in[3];
    const float* b1 = (const float*)d_in[4];
    const float* W2 = (const float*)d_in[5];
    const float* b2 = (const float*)d_in[6];
    float* out = (float*)d_out;

    const int EB  = (NE + 255) / 256;       // 6250
    const int VB  = (NN + 255) / 256;       // 391
    const int G1B = (NN + GR - 1) / GR;     // 391
    const int G2B = (NN + G2R - 1) / G2R;   // 782
    const int AB  = (NN * 32 + 255) / 256;  // 12500

    cudaFuncSetAttribute(k_gemm1, cudaFuncAttributeMaxDynamicSharedMemorySize, G1_SMEM);
    cudaFuncSetAttribute(k_gemm2, cudaFuncAttributeMaxDynamicSharedMemorySize, G2_SMEM);

    k_init<<<VB, 256>>>((const long long*)ei);      // 0
    k_decode_deg<<<EB, 256>>>(ei, ew);              // 1
    k_scan<<<NBLK, SCAN_B>>>();                     // 2
    k_gemm1<<<G1B, 256, G1_SMEM>>>(x, W1);          // 3
    k_fill<<<EB, 256>>>(ew);                        // 4
    k_agg1<<<AB, 256>>>(b1);                        // 5  <- ncu -s 5 lands here
    k_gemm2<<<G2B, 256, G2_SMEM>>>(W2);             // 6
    k_agg2<<<AB, 256>>>(b2, out);                   // 7
}

// round 9
// speedup vs baseline: 1.8685x; 1.0692x over previous
#include <cuda_runtime.h>
#include <cuda_fp16.h>
#include <cuda_bf16.h>

#define NN 100000
#define NE 1600000
#define NF 128
#define NH 64
#define NC 40

#define SCAN_B 1024
#define NBLK ((NN + SCAN_B - 1) / SCAN_B)   // 98

#define GR 256        // rows per gemm1 block
#define APAD 136      // bf16 row stride in smem
#define G1_SMEM ((GR + NH) * APAD * 2)   // 87040 B

#define G2R 128       // rows per gemm2 block
#define A2PAD 72      // half row stride (144 B)
#define G2_SMEM ((G2R + NC) * A2PAD * 2) // 24192 B

// ---------------- scratch ----------------
__device__ int                 g_is64;
__device__ int                 g_src[NE];
__device__ int                 g_dst[NE];
__device__ unsigned long long  g_pack[NN];   // (cnt<<40) | fixedpoint(sum w, 2^32)
__device__ int                 g_rowptr[NN];
__device__ int                 g_fill[NN];   // after k_fill: == row end
__device__ float               g_dinv[NN];
__device__ int2                g_edge[NE];   // CSR: {src, float_bits(dinv[s]*w)}
__device__ __half2             g_h1h[NN * 32];  // h1 fp16 (128 B rows)
__device__ __half2             g_a1h[NN * 32];  // a1 fp16 (128 B rows)
__device__ __half              g_h2h[NN * NC];  // h2 fp16 (80 B rows)
__device__ volatile unsigned long long g_sstat[NBLK];  // lookback: flag<<63 | aggregate

// ---------------- init: zero pack + scan status + dtype detect ----------------
__global__ void k_init(const long long* __restrict__ ei) {
    int i = blockIdx.x * blockDim.x + threadIdx.x;
    if (i < NN) g_pack[i] = 0ull;
    if (i < NBLK) g_sstat[i] = 0ull;
    if (blockIdx.x == 0) {
        __shared__ int ok;
        if (threadIdx.x == 0) ok = 1;
        __syncthreads();
        long long v = ei[threadIdx.x];   // 256 leading values
        if (!(v >= 0 && v < (long long)NN)) atomicAnd(&ok, 0);
        __syncthreads();
        if (threadIdx.x == 0) g_is64 = ok;
    }
}

// ---------------- fused decode + packed degree/count ----------------
__global__ void k_decode_deg(const void* __restrict__ ei, const float* __restrict__ w) {
    int e = blockIdx.x * blockDim.x + threadIdx.x;
    if (e >= NE) return;
    int s, d;
    if (g_is64) {
        const long long* p = (const long long*)ei;
        s = (int)p[e]; d = (int)p[NE + e];
    } else {
        const int* p = (const int*)ei;
        s = p[e]; d = p[NE + e];
    }
    g_src[e] = s;
    g_dst[e] = d;
    unsigned long long add = (1ull << 40) |
        (unsigned long long)(w[e] * 4294967296.0f);
    atomicAdd(&g_pack[d], add);
}

// ---------------- single-pass scan (decoupled lookback) + dinv ----------------
__global__ __launch_bounds__(SCAN_B) void k_scan() {
    int b = blockIdx.x, t = threadIdx.x;
    int gid = b * SCAN_B + t;
    int v = (gid < NN) ? (int)(g_pack[gid] >> 40) : 0;

    int lane = t & 31, wid = t >> 5;
    int incl = v;
    #pragma unroll
    for (int o = 1; o < 32; o <<= 1) {
        int u = __shfl_up_sync(0xffffffffu, incl, o);
        if (lane >= o) incl += u;
    }
    __shared__ int ws[32];
    if (lane == 31) ws[wid] = incl;
    __syncthreads();
    if (wid == 0) {
        int s = ws[lane];
        #pragma unroll
        for (int o = 1; o < 32; o <<= 1) {
            int u = __shfl_up_sync(0xffffffffu, s, o);
            if (lane >= o) s += u;
        }
        ws[lane] = s;
    }
    __syncthreads();
    if (wid > 0) incl += ws[wid - 1];
    int total = ws[31];

    if (t == 0)
        atomicExch((unsigned long long*)&g_sstat[b],
                   (1ull << 63) | (unsigned long long)total);

    __shared__ int boff_s;
    if (wid == 0) {
        int run = 0;
        for (int i = lane; i < b; i += 32) {
            unsigned long long s;
            do { s = g_sstat[i]; } while (!(s >> 63));
            run += (int)(s & 0x7FFFFFFFFFFFFFFFull);
        }
        #pragma unroll
        for (int o = 16; o > 0; o >>= 1)
            run += __shfl_xor_sync(0xffffffffu, run, o);
        if (lane == 0) boff_s = run;
    }
    __syncthreads();

    if (gid < NN) {
        int rp = boff_s + incl - v;
        g_rowptr[gid] = rp;
        g_fill[gid]   = rp;
        float degw = (float)(g_pack[gid] & 0xFFFFFFFFFFull) * (1.0f / 4294967296.0f);
        g_dinv[gid] = rsqrtf(degw + 1.0f);
    }
}

// ---------------- CSR fill (norm WITHOUT dinv[d] — factored into agg) ----------
__global__ void k_fill(const float* __restrict__ w) {
    int e = blockIdx.x * blockDim.x + threadIdx.x;
    if (e >= NE) return;
    int s = g_src[e], d = g_dst[e];
    int pos = atomicAdd(&g_fill[d], 1);
    float nv = g_dinv[s] * w[e];
    g_edge[pos] = make_int2(s, __float_as_int(nv));
}

// ---------------- mma helpers ----------------
__device__ __forceinline__ void mma16816bf(float* d,
                                           unsigned a0, unsigned a1, unsigned a2, unsigned a3,
                                           unsigned b0, unsigned b1) {
    asm volatile(
        "mma.sync.aligned.m16n8k16.row.col.f32.bf16.bf16.f32 "
        "{%0,%1,%2,%3}, {%4,%5,%6,%7}, {%8,%9}, {%0,%1,%2,%3};"
        : "+f"(d[0]), "+f"(d[1]), "+f"(d[2]), "+f"(d[3])
        : "r"(a0), "r"(a1), "r"(a2), "r"(a3), "r"(b0), "r"(b1));
}
__device__ __forceinline__ void mma16816h(float* d,
                                          unsigned a0, unsigned a1, unsigned a2, unsigned a3,
                                          unsigned b0, unsigned b1) {
    asm volatile(
        "mma.sync.aligned.m16n8k16.row.col.f32.f16.f16.f32 "
        "{%0,%1,%2,%3}, {%4,%5,%6,%7}, {%8,%9}, {%0,%1,%2,%3};"
        : "+f"(d[0]), "+f"(d[1]), "+f"(d[2]), "+f"(d[3])
        : "r"(a0), "r"(a1), "r"(a2), "r"(a3), "r"(b0), "r"(b1));
}

// ---------------- GEMM1: 512 threads, 16 warps x m16, GR=256 ------------------
__global__ __launch_bounds__(512) void k_gemm1(const float* __restrict__ x,
                                               const float* __restrict__ W1) {
    extern __shared__ __nv_bfloat16 sh[];
    __nv_bfloat16* As = sh;                  // [GR][APAD]
    __nv_bfloat16* Ws = sh + GR * APAD;      // [NH][APAD]  (W transposed: [n][k])
    int tid = threadIdx.x;
    int row0 = blockIdx.x * GR;

    const float4* W4 = (const float4*)W1;
    for (int i = tid; i < (NF * NH) / 4; i += 512) {
        int idx = i * 4;
        int k = idx / NH;
        int n = idx % NH;
        float4 w = W4[i];
        Ws[(n + 0) * APAD + k] = __float2bfloat16(w.x);
        Ws[(n + 1) * APAD + k] = __float2bfloat16(w.y);
        Ws[(n + 2) * APAD + k] = __float2bfloat16(w.z);
        Ws[(n + 3) * APAD + k] = __float2bfloat16(w.w);
    }

    const float4* x4 = (const float4*)x;
    #pragma unroll
    for (int it = 0; it < GR * 32 / 512; it++) {   // 16 iters
        int i  = tid + 512 * it;
        int r  = i >> 5;
        int c4 = i & 31;
        int gr = row0 + r;
        float4 v = (gr < NN) ? x4[(size_t)gr * 32 + c4] : make_float4(0.f, 0.f, 0.f, 0.f);
        __nv_bfloat162 p0 = __float22bfloat162_rn(make_float2(v.x, v.y));
        __nv_bfloat162 p1 = __float22bfloat162_rn(make_float2(v.z, v.w));
        *(__nv_bfloat162*)&As[r * APAD + c4 * 4]     = p0;
        *(__nv_bfloat162*)&As[r * APAD + c4 * 4 + 2] = p1;
    }
    __syncthreads();

    int w    = tid >> 5;      // 0..15
    int lane = tid & 31;
    int g    = lane >> 2;
    int tg   = lane & 3;
    int mrow0 = w * 16;       // 16 rows per warp x 16 warps = 256

    float acc[8][4];
    #pragma unroll
    for (int nt = 0; nt < 8; nt++)
        #pragma unroll
        for (int c = 0; c < 4; c++) acc[nt][c] = 0.f;

    #pragma unroll
    for (int ks = 0; ks < NF / 16; ks++) {
        int k0 = ks * 16;
        unsigned a0 = *(const unsigned*)&As[(mrow0 + g)     * APAD + k0 + tg * 2];
        unsigned a1 = *(const unsigned*)&As[(mrow0 + g + 8) * APAD + k0 + tg * 2];
        unsigned a2 = *(const unsigned*)&As[(mrow0 + g)     * APAD + k0 + tg * 2 + 8];
        unsigned a3 = *(const unsigned*)&As[(mrow0 + g + 8) * APAD + k0 + tg * 2 + 8];
        #pragma unroll
        for (int nt = 0; nt < 8; nt++) {
            unsigned b0 = *(const unsigned*)&Ws[(nt * 8 + g) * APAD + k0 + tg * 2];
            unsigned b1 = *(const unsigned*)&Ws[(nt * 8 + g) * APAD + k0 + tg * 2 + 8];
            mma16816bf(acc[nt], a0, a1, a2, a3, b0, b1);
        }
    }

    int rA = row0 + mrow0 + g;
    int rB = rA + 8;
    #pragma unroll
    for (int nt = 0; nt < 8; nt++) {
        int colh2 = nt * 4 + tg;
        if (rA < NN)
            g_h1h[(size_t)rA * 32 + colh2] = __floats2half2_rn(acc[nt][0], acc[nt][1]);
        if (rB < NN)
            g_h1h[(size_t)rB * 32 + colh2] = __floats2half2_rn(acc[nt][2], acc[nt][3]);
    }
}

// ---------------- AGG1: fp16 gather + bias + relu -> a1 fp16 -------------------
__global__ __launch_bounds__(256) void k_agg1(const float* __restrict__ b1) {
    int node = (blockIdx.x * blockDim.x + threadIdx.x) >> 5;
    int lane = threadIdx.x & 31;
    if (node >= NN) return;
    int beg = g_rowptr[node];
    int end = g_fill[node];
    float di = g_dinv[node];
    float2 hf = __half22float2(g_h1h[(size_t)node * 32 + lane]);
    // accumulate in units of dinv[d]^-1; multiply by di at the end
    float a0 = di * hf.x;
    float a1 = di * hf.y;

    int e = beg;
    for (; e + 3 < end; e += 4) {
        int2 ed[4];
        __half2 v[4];
        #pragma unroll
        for (int j = 0; j < 4; j++) ed[j] = g_edge[e + j];
        #pragma unroll
        for (int j = 0; j < 4; j++) v[j] = g_h1h[(size_t)ed[j].x * 32 + lane];
        #pragma unroll
        for (int j = 0; j < 4; j++) {
            float n = __int_as_float(ed[j].y);
            float2 f = __half22float2(v[j]);
            a0 = fmaf(n, f.x, a0);
            a1 = fmaf(n, f.y, a1);
        }
    }
    for (; e < end; e++) {
        int2 ed = g_edge[e];
        float n = __int_as_float(ed.y);
        float2 f = __half22float2(g_h1h[(size_t)ed.x * 32 + lane]);
        a0 = fmaf(n, f.x, a0);
        a1 = fmaf(n, f.y, a1);
    }
    float2 bb = *(const float2*)&b1[2 * lane];
    a0 = fmaxf(fmaf(di, a0, bb.x), 0.f);
    a1 = fmaxf(fmaf(di, a1, bb.y), 0.f);
    g_a1h[(size_t)node * 32 + lane] = __floats2half2_rn(a0, a1);
}

// ---------------- GEMM2: h2 = a1 @ W2 via fp16 mma, fp16 output ----------------
__global__ __launch_bounds__(256) void k_gemm2(const float* __restrict__ W2) {
    extern __shared__ __half sh2[];
    __half* As = sh2;                    // [G2R][A2PAD]
    __half* Ws = sh2 + G2R * A2PAD;      // [NC][A2PAD]
    int tid = threadIdx.x;
    int row0 = blockIdx.x * G2R;

    for (int i = tid; i < NH * NC; i += 256) {
        int k = i / NC, n = i % NC;
        Ws[n * A2PAD + k] = __float2half(W2[i]);
    }
    const uint4* a4 = (const uint4*)g_a1h;
    #pragma unroll
    for (int it = 0; it < G2R * 8 / 256; it++) {
        int i = tid + 256 * it;
        int r = i >> 3;
        int c = i & 7;
        int gr = row0 + r;
        uint4 v = (gr < NN) ? a4[(size_t)gr * 8 + c] : make_uint4(0u, 0u, 0u, 0u);
        *(uint4*)&As[r * A2PAD + c * 8] = v;
    }
    __syncthreads();

    int w    = tid >> 5;
    int lane = tid & 31;
    int g    = lane >> 2;
    int tg   = lane & 3;
    int mrow0 = w * 16;

    float acc[5][4];
    #pragma unroll
    for (int nt = 0; nt < 5; nt++)
        #pragma unroll
        for (int c = 0; c < 4; c++) acc[nt][c] = 0.f;

    #pragma unroll
    for (int ks = 0; ks < NH / 16; ks++) {
        int k0 = ks * 16;
        unsigned a0 = *(const unsigned*)&As[(mrow0 + g)     * A2PAD + k0 + tg * 2];
        unsigned a1 = *(const unsigned*)&As[(mrow0 + g + 8) * A2PAD + k0 + tg * 2];
        unsigned a2 = *(const unsigned*)&As[(mrow0 + g)     * A2PAD + k0 + tg * 2 + 8];
        unsigned a3 = *(const unsigned*)&As[(mrow0 + g + 8) * A2PAD + k0 + tg * 2 + 8];
        #pragma unroll
        for (int nt = 0; nt < 5; nt++) {
            unsigned b0 = *(const unsigned*)&Ws[(nt * 8 + g) * A2PAD + k0 + tg * 2];
            unsigned b1 = *(const unsigned*)&Ws[(nt * 8 + g) * A2PAD + k0 + tg * 2 + 8];
            mma16816h(acc[nt], a0, a1, a2, a3, b0, b1);
        }
    }

    int rA = row0 + mrow0 + g;
    int rB = rA + 8;
    #pragma unroll
    for (int nt = 0; nt < 5; nt++) {
        int col = nt * 8 + tg * 2;
        if (rA < NN)
            *(__half2*)&g_h2h[(size_t)rA * NC + col] = __floats2half2_rn(acc[nt][0], acc[nt][1]);
        if (rB < NN)
            *(__half2*)&g_h2h[(size_t)rB * NC + col] = __floats2half2_rn(acc[nt][2], acc[nt][3]);
    }
}

// ---------------- AGG2 (fp16 gather) + bias + log_softmax ----------------------
__global__ __launch_bounds__(256) void k_agg2(const float* __restrict__ b2,
                                              float* __restrict__ out) {
    int node = (blockIdx.x * blockDim.x + threadIdx.x) >> 5;
    int lane = threadIdx.x & 31;
    if (node >= NN) return;
    bool hi = (lane < NC - 32);
    int beg = g_rowptr[node];
    int end = g_fill[node];
    float di = g_dinv[node];
    const __half* hn = &g_h2h[(size_t)node * NC];
    float a0 = di * __half2float(hn[lane]);
    float a1 = hi ? di * __half2float(hn[32 + lane]) : 0.f;

    int e = beg;
    for (; e + 3 < end; e += 4) {
        int2 ed[4];
        __half v[4], u[4];
        #pragma unroll
        for (int j = 0; j < 4; j++) ed[j] = g_edge[e + j];
        #pragma unroll
        for (int j = 0; j < 4; j++) {
            const __half* p = &g_h2h[(size_t)ed[j].x * NC];
            v[j] = p[lane];
            u[j] = hi ? p[32 + lane] : __half(0.f);
        }
        #pragma unroll
        for (int j = 0; j < 4; j++) {
            float n = __int_as_float(ed[j].y);
            a0 = fmaf(n, __half2float(v[j]), a0);
            if (hi) a1 = fmaf(n, __half2float(u[j]), a1);
        }
    }
    for (; e < end; e++) {
        int2 ed = g_edge[e];
        const __half* p = &g_h2h[(size_t)ed.x * NC];
        float n = __int_as_float(ed.y);
        a0 = fmaf(n, __half2float(p[lane]), a0);
        if (hi) a1 = fmaf(n, __half2float(p[32 + lane]), a1);
    }
    a0 = fmaf(di, a0, b2[lane]);
    if (hi) a1 = fmaf(di, a1, b2[32 + lane]);

    float m = hi ? fmaxf(a0, a1) : a0;
    #pragma unroll
    for (int off = 16; off > 0; off >>= 1)
        m = fmaxf(m, __shfl_xor_sync(0xffffffffu, m, off));
    float s = __expf(a0 - m) + (hi ? __expf(a1 - m) : 0.f);
    #pragma unroll
    for (int off = 16; off > 0; off >>= 1)
        s += __shfl_xor_sync(0xffffffffu, s, off);
    float lse = m + __logf(s);

    float* o = out + (size_t)node * NC;
    o[lane] = a0 - lse;
    if (hi) o[32 + lane] = a1 - lse;
}

// ---------------- launcher ----------------
extern "C" void kernel_launch(void* const* d_in, const int* in_sizes, int n_in,
                              void* d_out, int out_size) {
    const float* x  = (const float*)d_in[0];
    const void*  ei = d_in[1];
    const float* ew = (const float*)d_in[2];
    const float* W1 = (const float*)d_in[3];
    const float* b1 = (const float*)d_in[4];
    const float* W2 = (const float*)d_in[5];
    const float* b2 = (const float*)d_in[6];
    float* out = (float*)d_out;

    const int EB  = (NE + 255) / 256;       // 6250
    const int VB  = (NN + 255) / 256;       // 391
    const int G1B = (NN + GR - 1) / GR;     // 391
    const int G2B = (NN + G2R - 1) / G2R;   // 782
    const int AB  = (NN * 32 + 255) / 256;  // 12500

    cudaFuncSetAttribute(k_gemm1, cudaFuncAttributeMaxDynamicSharedMemorySize, G1_SMEM);
    cudaFuncSetAttribute(k_gemm2, cudaFuncAttributeMaxDynamicSharedMemorySize, G2_SMEM);

    k_init<<<VB, 256>>>((const long long*)ei);      // 0
    k_decode_deg<<<EB, 256>>>(ei, ew);              // 1
    k_scan<<<NBLK, SCAN_B>>>();                     // 2
    k_gemm1<<<G1B, 512, G1_SMEM>>>(x, W1);          // 3
    k_fill<<<EB, 256>>>(ew);                        // 4
    k_agg1<<<AB, 256>>>(b1);                        // 5  <- ncu lands here
    k_gemm2<<<G2B, 256, G2_SMEM>>>(W2);             // 6
    k_agg2<<<AB, 256>>>(b2, out);                   // 7
}